// round 4
// baseline (speedup 1.0000x reference)
#include <cuda_runtime.h>
#include <math.h>

#define NC 512
#define NPIX 1024

// ---------------- scratch (no allocations allowed) ----------------
__device__ float g_y[NC];                 // channel means
__device__ float g_s[NC];                 // SE scales
__device__ float g_A[32 * 32];            // row-stochastic gaussian matrix A[i][x]
__device__ float g_f0t[NPIX * NC];        // f0 transposed: [pix][ch]
__device__ float g_sigt[NPIX * NC];       // sigmoid(f0): [pix][ch]
__device__ float g_cat[2 * NPIX * NC];    // [0..512K): gus flat, [512K..1M): csa flat

// ---------------- 1. per-channel mean (blocks 0..511) + gaussian matrix A (block 512) ----------------
__global__ void k_mean_initA(const float* __restrict__ x) {
    int t = threadIdx.x;
    if (blockIdx.x < 512) {
        int c = blockIdx.x;
        float4 v = ((const float4*)(x + c * 1024))[t];
        float s = v.x + v.y + v.z + v.w;
        #pragma unroll
        for (int o = 16; o; o >>= 1) s += __shfl_down_sync(0xffffffffu, s, o);
        __shared__ float ws[8];
        if ((t & 31) == 0) ws[t >> 5] = s;
        __syncthreads();
        if (t == 0) {
            float tot = 0.f;
            #pragma unroll
            for (int i = 0; i < 8; i++) tot += ws[i];
            g_y[c] = tot * (1.f / 1024.f);
        }
    } else {
        __shared__ double srow[32];
        if (t < 32) {
            double s = 0.0;
            for (int xx = 0; xx < 32; xx++) {
                double d = (double)(xx - t);
                s += exp(-d * d / 4.5);
            }
            srow[t] = s;
        }
        __syncthreads();
        for (int idx = t; idx < 1024; idx += 256) {
            int i = idx >> 5, xx = idx & 31;
            double d = (double)(xx - i);
            g_A[idx] = (float)(exp(-d * d / 4.5) / srow[i]);
        }
    }
}

// ---------------- 2. SE MLP: 512 -> 32 (relu) -> 512 (sigmoid) ----------------
__global__ void k_mlp(const float* __restrict__ w1, const float* __restrict__ b1,
                      const float* __restrict__ w2, const float* __restrict__ b2) {
    __shared__ float sy[512];
    __shared__ float sh[32];
    int t = threadIdx.x;
    if (t < 512) sy[t] = g_y[t];
    __syncthreads();
    int r = t >> 5, lane = t & 31;   // 32 warps, one per hidden unit
    float a = 0.f;
    for (int c = lane; c < 512; c += 32) a += sy[c] * w1[r * 512 + c];
    #pragma unroll
    for (int o = 16; o; o >>= 1) a += __shfl_down_sync(0xffffffffu, a, o);
    if (lane == 0) sh[r] = fmaxf(a + b1[r], 0.f);
    __syncthreads();
    if (t < 512) {
        float acc = b2[t];
        #pragma unroll
        for (int rr = 0; rr < 32; rr++) acc += sh[rr] * w2[t * 32 + rr];
        g_s[t] = 1.f / (1.f + expf(-acc));
    }
}

// ---------------- 3. fused: gaussian pooling (blocks 0..511) + scale/transpose/sigmoid (512..1023) ----------------
__global__ void k_gauss_trans(const float* __restrict__ x) {
    __shared__ float sbuf[4096];
    int t = threadIdx.x;
    if (blockIdx.x < 512) {
        float* F   = sbuf;
        float* T   = sbuf + 1024;
        float* sA  = sbuf + 2048;
        float* sAt = sbuf + 3072;
        int c = blockIdx.x;
        float s = g_s[c];
        for (int i = t; i < 1024; i += 256) {
            F[i] = x[c * 1024 + i] * s;
            float a = g_A[i];
            sA[i] = a;                                // sA[k*32+y]  = A[k][y]
            sAt[(i & 31) * 32 + (i >> 5)] = a;        // sAt[y*32+k] = A[k][y]
        }
        __syncthreads();
        for (int idx = t; idx < 1024; idx += 256) {   // T[x][k] = sum_y A[k][y]*F[x][y]
            int xx = idx >> 5, k = idx & 31;
            float acc = 0.f;
            #pragma unroll
            for (int y = 0; y < 32; y++) acc += sAt[y * 32 + k] * F[xx * 32 + y];
            T[idx] = acc;
        }
        __syncthreads();
        for (int idx = t; idx < 1024; idx += 256) {   // B[i][k] = sum_x A[i][x]*T[x][k]
            int i = idx >> 5, k = idx & 31;
            float acc = 0.f;
            #pragma unroll
            for (int xx = 0; xx < 32; xx++) acc += sA[i * 32 + xx] * T[xx * 32 + k];
            g_cat[idx * 512 + c] = acc;
        }
    } else {
        float (*tile)[33] = (float(*)[33])sbuf;
        int bid = blockIdx.x - 512;
        int p0 = (bid & 31) * 32, c0 = (bid >> 5) * 32;
        int tx = t & 31, ty = t >> 5;
        #pragma unroll
        for (int j = 0; j < 4; j++) {
            int ch = c0 + ty + j * 8;
            tile[ty + j * 8][tx] = x[ch * 1024 + p0 + tx] * g_s[ch];
        }
        __syncthreads();
        #pragma unroll
        for (int j = 0; j < 4; j++) {
            int p = p0 + ty + j * 8;
            float v = tile[tx][ty + j * 8];
            g_f0t[p * 512 + c0 + tx] = v;
            g_sigt[p * 512 + c0 + tx] = 1.f / (1.f + expf(-v));
        }
    }
}

// ---------------- 4. 3x3 patch-correlation attention: constant-offset addressing ----------------
__global__ void k_csa() {
    int pix = blockIdx.x, pi = pix >> 5, pj = pix & 31;
    int t = threadIdx.x;
    int base = pix * 512 + t;          // channels c0=t, c1=t+256
    __shared__ float wsum[8][9];
    __shared__ float sa[9];

    float sc0 = g_sigt[base];
    float sc1 = g_sigt[base + 256];

    bool okU = pi > 0, okD = pi < 31, okL = pj > 0, okR = pj < 31;
    bool ok[9];
    ok[0] = okU && okL; ok[1] = okU; ok[2] = okU && okR;
    ok[3] = okL;        ok[4] = true; ok[5] = okR;
    ok[6] = okD && okL; ok[7] = okD; ok[8] = okD && okR;
    const int off[9] = { -33*512, -32*512, -31*512, -1*512, 0, 1*512, 31*512, 32*512, 33*512 };

    float acc[9];
    #pragma unroll
    for (int uv = 0; uv < 9; uv++) {
        acc[uv] = ok[uv]
            ? sc0 * g_sigt[base + off[uv]] + sc1 * g_sigt[base + off[uv] + 256]
            : 0.f;
    }
    #pragma unroll
    for (int uv = 0; uv < 9; uv++)
        #pragma unroll
        for (int o = 16; o; o >>= 1) acc[uv] += __shfl_down_sync(0xffffffffu, acc[uv], o);
    if ((t & 31) == 0) {
        #pragma unroll
        for (int uv = 0; uv < 9; uv++) wsum[t >> 5][uv] = acc[uv];
    }
    __syncthreads();
    // distributed softmax over 9 taps on warp 0
    if (t < 32) {
        float v = -1e30f;
        if (t < 9) {
            float s2 = 0.f;
            #pragma unroll
            for (int w = 0; w < 8; w++) s2 += wsum[w][t];
            v = s2 * (1.f / 512.f);
        }
        float m = v;
        #pragma unroll
        for (int o = 16; o; o >>= 1) m = fmaxf(m, __shfl_xor_sync(0xffffffffu, m, o));
        float e = (t < 9) ? expf(v - m) : 0.f;
        float tot = e;
        #pragma unroll
        for (int o = 16; o; o >>= 1) tot += __shfl_xor_sync(0xffffffffu, tot, o);
        if (t < 9) sa[t] = e / tot;
    }
    __syncthreads();

    float o0 = 0.f, o1 = 0.f;
    #pragma unroll
    for (int uv = 0; uv < 9; uv++) {
        if (ok[uv]) {
            float a = sa[uv];
            o0 += a * g_f0t[base + off[uv]];
            o1 += a * g_f0t[base + off[uv] + 256];
        }
    }
    g_cat[524288 + base] = o0;
    g_cat[524288 + base + 256] = o1;
}

// ---------------- 5. down GEMM: 3xTF32 tensor-core ----------------
// z[512,1024] = W[512,1024] @ cat[1024,1024]
// Block tile 64x64, 8 warps (256 thr), warp tile 16x32 (warps: 4 in M, 2 in N).
// 3xTF32: W = Whi+Wlo, cat = Bhi+Blo; acc += Whi*Bhi + Whi*Blo + Wlo*Bhi.

#define MMA_TF32(d, a0, a1, a2, a3, b0, b1)                                  \
    asm volatile("mma.sync.aligned.m16n8k8.row.col.f32.tf32.tf32.f32 "       \
                 "{%0,%1,%2,%3}, {%4,%5,%6,%7}, {%8,%9}, {%0,%1,%2,%3};"     \
                 : "+f"(d[0]), "+f"(d[1]), "+f"(d[2]), "+f"(d[3])            \
                 : "r"(a0), "r"(a1), "r"(a2), "r"(a3), "r"(b0), "r"(b1))

__device__ __forceinline__ void tf32_split(float f, unsigned& hi, unsigned& lo) {
    unsigned h;
    asm("cvt.rna.tf32.f32 %0, %1;" : "=r"(h) : "f"(f));
    hi = h;
    lo = __float_as_uint(f - __uint_as_float(h));
}

#define LDP 65   // padded row stride (floats) for 64-wide smem tiles

__global__ void k_gemm(const float* __restrict__ Wd, float* __restrict__ out) {
    __shared__ float sAh[16 * LDP], sAl[16 * LDP];   // A: [k][m], 16x64
    __shared__ float sBh[16 * LDP], sBl[16 * LDP];   // B: [k][n], 16x64
    int t = threadIdx.x;
    int w = t >> 5, lane = t & 31;
    int g = lane >> 2, q = lane & 3;                 // groupID, tid-in-group
    int mw = w >> 1, nw = w & 1;                     // warp grid 4(M) x 2(N)
    int mbase = mw * 16, nbase = nw * 32;
    int m0 = blockIdx.y * 64, n0 = blockIdx.x * 64;

    const unsigned* uAh = (const unsigned*)sAh;
    const unsigned* uAl = (const unsigned*)sAl;
    const unsigned* uBh = (const unsigned*)sBh;
    const unsigned* uBl = (const unsigned*)sBl;

    // load indices: A tile 64 rows x 16 k (1 float4/thread), B tile 16 k x 64 n
    int arow = t >> 2, ac4 = (t & 3) * 4;
    int brow = t >> 4, bc4 = (t & 15) * 4;
    const float* wp = Wd + (m0 + arow) * 1024 + ac4;
    const float* bp = g_cat + brow * 1024 + n0 + bc4;

    float acc[4][4] = {};   // 4 n-tiles x 4 c-regs (warp tile 16x32)

    for (int k0 = 0; k0 < 1024; k0 += 16) {
        float4 wa = *(const float4*)(wp + k0);
        float4 cb = *(const float4*)(bp + k0 * 1024);
        __syncthreads();
        {
            unsigned h, l;
            tf32_split(wa.x, h, l); sAh[(ac4+0)*LDP + arow] = __uint_as_float(h); sAl[(ac4+0)*LDP + arow] = __uint_as_float(l);
            tf32_split(wa.y, h, l); sAh[(ac4+1)*LDP + arow] = __uint_as_float(h); sAl[(ac4+1)*LDP + arow] = __uint_as_float(l);
            tf32_split(wa.z, h, l); sAh[(ac4+2)*LDP + arow] = __uint_as_float(h); sAl[(ac4+2)*LDP + arow] = __uint_as_float(l);
            tf32_split(wa.w, h, l); sAh[(ac4+3)*LDP + arow] = __uint_as_float(h); sAl[(ac4+3)*LDP + arow] = __uint_as_float(l);
            tf32_split(cb.x, h, l); sBh[brow*LDP + bc4+0] = __uint_as_float(h); sBl[brow*LDP + bc4+0] = __uint_as_float(l);
            tf32_split(cb.y, h, l); sBh[brow*LDP + bc4+1] = __uint_as_float(h); sBl[brow*LDP + bc4+1] = __uint_as_float(l);
            tf32_split(cb.z, h, l); sBh[brow*LDP + bc4+2] = __uint_as_float(h); sBl[brow*LDP + bc4+2] = __uint_as_float(l);
            tf32_split(cb.w, h, l); sBh[brow*LDP + bc4+3] = __uint_as_float(h); sBl[brow*LDP + bc4+3] = __uint_as_float(l);
        }
        __syncthreads();
        #pragma unroll
        for (int kk = 0; kk < 16; kk += 8) {
            int ao = (kk + q) * LDP + mbase + g;
            unsigned a0h = uAh[ao],           a1h = uAh[ao + 8];
            unsigned a2h = uAh[ao + 4 * LDP], a3h = uAh[ao + 4 * LDP + 8];
            unsigned a0l = uAl[ao],           a1l = uAl[ao + 8];
            unsigned a2l = uAl[ao + 4 * LDP], a3l = uAl[ao + 4 * LDP + 8];
            #pragma unroll
            for (int nt = 0; nt < 4; nt++) {
                int bo = (kk + q) * LDP + nbase + nt * 8 + g;
                unsigned b0h = uBh[bo], b1h = uBh[bo + 4 * LDP];
                unsigned b0l = uBl[bo], b1l = uBl[bo + 4 * LDP];
                MMA_TF32(acc[nt], a0h, a1h, a2h, a3h, b0h, b1h);
                MMA_TF32(acc[nt], a0h, a1h, a2h, a3h, b0l, b1l);
                MMA_TF32(acc[nt], a0l, a1l, a2l, a3l, b0h, b1h);
            }
        }
    }
    // epilogue: c0,c1 at (row, 2q / 2q+1); c2,c3 at (row+8, ...)
    int orow = m0 + mbase + g;
    #pragma unroll
    for (int nt = 0; nt < 4; nt++) {
        int ocol = n0 + nbase + nt * 8 + 2 * q;
        *(float2*)(out + orow * 1024 + ocol)       = make_float2(acc[nt][0], acc[nt][1]);
        *(float2*)(out + (orow + 8) * 1024 + ocol) = make_float2(acc[nt][2], acc[nt][3]);
    }
}

// ---------------- 6. instance norm + leaky relu (in place) ----------------
__global__ void k_norm(float* __restrict__ out) {
    int o = blockIdx.x, t = threadIdx.x;
    float4* row = (float4*)(out + o * 1024);
    float4 v = row[t];
    float s = v.x + v.y + v.z + v.w;
    float ss = v.x * v.x + v.y * v.y + v.z * v.z + v.w * v.w;
    #pragma unroll
    for (int off = 16; off; off >>= 1) {
        s  += __shfl_down_sync(0xffffffffu, s, off);
        ss += __shfl_down_sync(0xffffffffu, ss, off);
    }
    __shared__ float w1s[8], w2s[8];
    __shared__ float smean, sinv;
    if ((t & 31) == 0) { w1s[t >> 5] = s; w2s[t >> 5] = ss; }
    __syncthreads();
    if (t == 0) {
        float ts = 0.f, tss = 0.f;
        #pragma unroll
        for (int i = 0; i < 8; i++) { ts += w1s[i]; tss += w2s[i]; }
        float mu = ts * (1.f / 1024.f);
        float var = tss * (1.f / 1024.f) - mu * mu;
        smean = mu;
        sinv = 1.f / sqrtf(var + 1e-5f);
    }
    __syncthreads();
    float mu = smean, inv = sinv;
    float a;
    a = (v.x - mu) * inv; v.x = a >= 0.f ? a : 0.2f * a;
    a = (v.y - mu) * inv; v.y = a >= 0.f ? a : 0.2f * a;
    a = (v.z - mu) * inv; v.z = a >= 0.f ? a : 0.2f * a;
    a = (v.w - mu) * inv; v.w = a >= 0.f ? a : 0.2f * a;
    row[t] = v;
}

// ---------------- launch ----------------
extern "C" void kernel_launch(void* const* d_in, const int* in_sizes, int n_in,
                              void* d_out, int out_size) {
    const float* x  = (const float*)d_in[0];   // (1,512,32,32)
    const float* w1 = (const float*)d_in[1];   // (32,512)
    const float* b1 = (const float*)d_in[2];   // (32)
    const float* w2 = (const float*)d_in[3];   // (512,32)
    const float* b2 = (const float*)d_in[4];   // (512)
    const float* dw = (const float*)d_in[5];   // (512,1024)
    float* out = (float*)d_out;                // (1,512,32,32) fp32

    k_mean_initA<<<513, 256>>>(x);
    k_mlp<<<1, 1024>>>(w1, b1, w2, b2);
    k_gauss_trans<<<1024, 256>>>(x);
    k_csa<<<1024, 256>>>();
    k_gemm<<<dim3(16, 8), 256>>>(dw, out);
    k_norm<<<512, 256>>>(out);
}

// round 5
// speedup vs baseline: 1.5349x; 1.5349x over previous
#include <cuda_runtime.h>
#include <math.h>

#define NC 512
#define NPIX 1024

// ---------------- scratch (no allocations allowed) ----------------
__device__ float g_y[NC];                 // channel means
__device__ float g_s[NC];                 // SE scales
__device__ float g_A[32 * 32];            // row-stochastic gaussian matrix A[i][x]
__device__ float g_f0t[NPIX * NC];        // f0 transposed: [pix][ch]
__device__ float g_sigt[NPIX * NC];       // sigmoid(f0): [pix][ch]
__device__ float g_cat[2 * NPIX * NC];    // [0..512K): gus flat, [512K..1M): csa flat

// ---------------- 1. per-channel mean (blocks 0..511) + gaussian matrix A (block 512) ----------------
__global__ void k_mean_initA(const float* __restrict__ x) {
    int t = threadIdx.x;
    if (blockIdx.x < 512) {
        int c = blockIdx.x;
        float4 v = ((const float4*)(x + c * 1024))[t];
        float s = v.x + v.y + v.z + v.w;
        #pragma unroll
        for (int o = 16; o; o >>= 1) s += __shfl_down_sync(0xffffffffu, s, o);
        __shared__ float ws[8];
        if ((t & 31) == 0) ws[t >> 5] = s;
        __syncthreads();
        if (t == 0) {
            float tot = 0.f;
            #pragma unroll
            for (int i = 0; i < 8; i++) tot += ws[i];
            g_y[c] = tot * (1.f / 1024.f);
        }
    } else {
        __shared__ double srow[32];
        if (t < 32) {
            double s = 0.0;
            for (int xx = 0; xx < 32; xx++) {
                double d = (double)(xx - t);
                s += exp(-d * d / 4.5);
            }
            srow[t] = s;
        }
        __syncthreads();
        for (int idx = t; idx < 1024; idx += 256) {
            int i = idx >> 5, xx = idx & 31;
            double d = (double)(xx - i);
            g_A[idx] = (float)(exp(-d * d / 4.5) / srow[i]);
        }
    }
}

// ---------------- 2. SE MLP: 512 -> 32 (relu) -> 512 (sigmoid) ----------------
__global__ void k_mlp(const float* __restrict__ w1, const float* __restrict__ b1,
                      const float* __restrict__ w2, const float* __restrict__ b2) {
    __shared__ float sy[512];
    __shared__ float sh[32];
    int t = threadIdx.x;
    if (t < 512) sy[t] = g_y[t];
    __syncthreads();
    int r = t >> 5, lane = t & 31;   // 32 warps, one per hidden unit
    float a = 0.f;
    for (int c = lane; c < 512; c += 32) a += sy[c] * w1[r * 512 + c];
    #pragma unroll
    for (int o = 16; o; o >>= 1) a += __shfl_down_sync(0xffffffffu, a, o);
    if (lane == 0) sh[r] = fmaxf(a + b1[r], 0.f);
    __syncthreads();
    if (t < 512) {
        float acc = b2[t];
        #pragma unroll
        for (int rr = 0; rr < 32; rr++) acc += sh[rr] * w2[t * 32 + rr];
        g_s[t] = 1.f / (1.f + expf(-acc));
    }
}

// ---------------- 3. fused: gaussian pooling (blocks 0..511) + scale/transpose/sigmoid (512..1023) ----------------
__global__ void k_gauss_trans(const float* __restrict__ x) {
    __shared__ float sbuf[4096];
    int t = threadIdx.x;
    if (blockIdx.x < 512) {
        float* F   = sbuf;
        float* T   = sbuf + 1024;
        float* sA  = sbuf + 2048;
        float* sAt = sbuf + 3072;
        int c = blockIdx.x;
        float s = g_s[c];
        for (int i = t; i < 1024; i += 256) {
            F[i] = x[c * 1024 + i] * s;
            float a = g_A[i];
            sA[i] = a;                                // sA[k*32+y]  = A[k][y]
            sAt[(i & 31) * 32 + (i >> 5)] = a;        // sAt[y*32+k] = A[k][y]
        }
        __syncthreads();
        for (int idx = t; idx < 1024; idx += 256) {   // T[x][k] = sum_y A[k][y]*F[x][y]
            int xx = idx >> 5, k = idx & 31;
            float acc = 0.f;
            #pragma unroll
            for (int y = 0; y < 32; y++) acc += sAt[y * 32 + k] * F[xx * 32 + y];
            T[idx] = acc;
        }
        __syncthreads();
        for (int idx = t; idx < 1024; idx += 256) {   // B[i][k] = sum_x A[i][x]*T[x][k]
            int i = idx >> 5, k = idx & 31;
            float acc = 0.f;
            #pragma unroll
            for (int xx = 0; xx < 32; xx++) acc += sA[i * 32 + xx] * T[xx * 32 + k];
            g_cat[idx * 512 + c] = acc;
        }
    } else {
        float (*tile)[33] = (float(*)[33])sbuf;
        int bid = blockIdx.x - 512;
        int p0 = (bid & 31) * 32, c0 = (bid >> 5) * 32;
        int tx = t & 31, ty = t >> 5;
        #pragma unroll
        for (int j = 0; j < 4; j++) {
            int ch = c0 + ty + j * 8;
            tile[ty + j * 8][tx] = x[ch * 1024 + p0 + tx] * g_s[ch];
        }
        __syncthreads();
        #pragma unroll
        for (int j = 0; j < 4; j++) {
            int p = p0 + ty + j * 8;
            float v = tile[tx][ty + j * 8];
            g_f0t[p * 512 + c0 + tx] = v;
            g_sigt[p * 512 + c0 + tx] = 1.f / (1.f + expf(-v));
        }
    }
}

// ---------------- 4. 3x3 patch-correlation attention: constant-offset addressing ----------------
__global__ void k_csa() {
    int pix = blockIdx.x, pi = pix >> 5, pj = pix & 31;
    int t = threadIdx.x;
    int base = pix * 512 + t;          // channels c0=t, c1=t+256
    __shared__ float wsum[8][9];
    __shared__ float sa[9];

    float sc0 = g_sigt[base];
    float sc1 = g_sigt[base + 256];

    bool okU = pi > 0, okD = pi < 31, okL = pj > 0, okR = pj < 31;
    bool ok[9];
    ok[0] = okU && okL; ok[1] = okU; ok[2] = okU && okR;
    ok[3] = okL;        ok[4] = true; ok[5] = okR;
    ok[6] = okD && okL; ok[7] = okD; ok[8] = okD && okR;
    const int off[9] = { -33*512, -32*512, -31*512, -1*512, 0, 1*512, 31*512, 32*512, 33*512 };

    float acc[9];
    #pragma unroll
    for (int uv = 0; uv < 9; uv++) {
        acc[uv] = ok[uv]
            ? sc0 * g_sigt[base + off[uv]] + sc1 * g_sigt[base + off[uv] + 256]
            : 0.f;
    }
    #pragma unroll
    for (int uv = 0; uv < 9; uv++)
        #pragma unroll
        for (int o = 16; o; o >>= 1) acc[uv] += __shfl_down_sync(0xffffffffu, acc[uv], o);
    if ((t & 31) == 0) {
        #pragma unroll
        for (int uv = 0; uv < 9; uv++) wsum[t >> 5][uv] = acc[uv];
    }
    __syncthreads();
    // distributed softmax over 9 taps on warp 0
    if (t < 32) {
        float v = -1e30f;
        if (t < 9) {
            float s2 = 0.f;
            #pragma unroll
            for (int w = 0; w < 8; w++) s2 += wsum[w][t];
            v = s2 * (1.f / 512.f);
        }
        float m = v;
        #pragma unroll
        for (int o = 16; o; o >>= 1) m = fmaxf(m, __shfl_xor_sync(0xffffffffu, m, o));
        float e = (t < 9) ? expf(v - m) : 0.f;
        float tot = e;
        #pragma unroll
        for (int o = 16; o; o >>= 1) tot += __shfl_xor_sync(0xffffffffu, tot, o);
        if (t < 9) sa[t] = e / tot;
    }
    __syncthreads();

    float o0 = 0.f, o1 = 0.f;
    #pragma unroll
    for (int uv = 0; uv < 9; uv++) {
        if (ok[uv]) {
            float a = sa[uv];
            o0 += a * g_f0t[base + off[uv]];
            o1 += a * g_f0t[base + off[uv] + 256];
        }
    }
    g_cat[524288 + base] = o0;
    g_cat[524288 + base + 256] = o1;
}

// ---------------- 5. down GEMM: FFMA, register double-buffered, Ktile=32 ----------------
// z[512,1024] = W[512,1024] @ cat[1024,1024]; 64x64 block tile, 256 threads, 4x4 micro-tile.
#define LDA 68   // padded k-major A tile stride (16B-aligned)

__global__ void k_gemm(const float* __restrict__ Wd, float* __restrict__ out) {
    __shared__ float As[32 * LDA];   // As[k][m], 32 x 64 (padded)
    __shared__ float Bs[32 * 64];    // Bs[k][n]
    int t = threadIdx.x;
    int tx = t & 15, ty = t >> 4;
    int m0 = blockIdx.y * 64, n0 = blockIdx.x * 64;

    // A loads: row = t>>3 (+32), kc = (t&7)*4  -> fully coalesced 128B/row
    int arow = t >> 3, akc = (t & 7) * 4;
    // B loads: krow = t>>4 (+16), nc = (t&15)*4 -> fully coalesced 256B/row
    int bkr = t >> 4, bnc = (t & 15) * 4;
    const float* wp = Wd + (m0 + arow) * 1024 + akc;
    const float* bp = g_cat + bkr * 1024 + n0 + bnc;

    float4 ra0, ra1, rb0, rb1;
    ra0 = *(const float4*)(wp);
    ra1 = *(const float4*)(wp + 32 * 1024);
    rb0 = *(const float4*)(bp);
    rb1 = *(const float4*)(bp + 16 * 1024);

    float acc[4][4] = {};

    #pragma unroll 1
    for (int kt = 0; kt < 32; kt++) {
        __syncthreads();
        // store prefetched tile to smem
        As[(akc + 0) * LDA + arow] = ra0.x;
        As[(akc + 1) * LDA + arow] = ra0.y;
        As[(akc + 2) * LDA + arow] = ra0.z;
        As[(akc + 3) * LDA + arow] = ra0.w;
        As[(akc + 0) * LDA + arow + 32] = ra1.x;
        As[(akc + 1) * LDA + arow + 32] = ra1.y;
        As[(akc + 2) * LDA + arow + 32] = ra1.z;
        As[(akc + 3) * LDA + arow + 32] = ra1.w;
        *(float4*)&Bs[bkr * 64 + bnc] = rb0;
        *(float4*)&Bs[(bkr + 16) * 64 + bnc] = rb1;
        __syncthreads();
        // prefetch next tile (overlaps with compute below)
        if (kt < 31) {
            int ko = (kt + 1) * 32;
            ra0 = *(const float4*)(wp + ko);
            ra1 = *(const float4*)(wp + ko + 32 * 1024);
            rb0 = *(const float4*)(bp + ko * 1024);
            rb1 = *(const float4*)(bp + (ko + 16) * 1024);
        }
        #pragma unroll
        for (int k = 0; k < 32; k++) {
            float4 a = *(float4*)&As[k * LDA + ty * 4];
            float4 b = *(float4*)&Bs[k * 64 + tx * 4];
            acc[0][0] += a.x * b.x; acc[0][1] += a.x * b.y; acc[0][2] += a.x * b.z; acc[0][3] += a.x * b.w;
            acc[1][0] += a.y * b.x; acc[1][1] += a.y * b.y; acc[1][2] += a.y * b.z; acc[1][3] += a.y * b.w;
            acc[2][0] += a.z * b.x; acc[2][1] += a.z * b.y; acc[2][2] += a.z * b.z; acc[2][3] += a.z * b.w;
            acc[3][0] += a.w * b.x; acc[3][1] += a.w * b.y; acc[3][2] += a.w * b.z; acc[3][3] += a.w * b.w;
        }
    }
    #pragma unroll
    for (int i = 0; i < 4; i++) {
        float4 r = make_float4(acc[i][0], acc[i][1], acc[i][2], acc[i][3]);
        *(float4*)(out + (m0 + ty * 4 + i) * 1024 + n0 + tx * 4) = r;
    }
}

// ---------------- 6. instance norm + leaky relu (in place) ----------------
__global__ void k_norm(float* __restrict__ out) {
    int o = blockIdx.x, t = threadIdx.x;
    float4* row = (float4*)(out + o * 1024);
    float4 v = row[t];
    float s = v.x + v.y + v.z + v.w;
    float ss = v.x * v.x + v.y * v.y + v.z * v.z + v.w * v.w;
    #pragma unroll
    for (int off = 16; off; off >>= 1) {
        s  += __shfl_down_sync(0xffffffffu, s, off);
        ss += __shfl_down_sync(0xffffffffu, ss, off);
    }
    __shared__ float w1s[8], w2s[8];
    __shared__ float smean, sinv;
    if ((t & 31) == 0) { w1s[t >> 5] = s; w2s[t >> 5] = ss; }
    __syncthreads();
    if (t == 0) {
        float ts = 0.f, tss = 0.f;
        #pragma unroll
        for (int i = 0; i < 8; i++) { ts += w1s[i]; tss += w2s[i]; }
        float mu = ts * (1.f / 1024.f);
        float var = tss * (1.f / 1024.f) - mu * mu;
        smean = mu;
        sinv = 1.f / sqrtf(var + 1e-5f);
    }
    __syncthreads();
    float mu = smean, inv = sinv;
    float a;
    a = (v.x - mu) * inv; v.x = a >= 0.f ? a : 0.2f * a;
    a = (v.y - mu) * inv; v.y = a >= 0.f ? a : 0.2f * a;
    a = (v.z - mu) * inv; v.z = a >= 0.f ? a : 0.2f * a;
    a = (v.w - mu) * inv; v.w = a >= 0.f ? a : 0.2f * a;
    row[t] = v;
}

// ---------------- launch ----------------
extern "C" void kernel_launch(void* const* d_in, const int* in_sizes, int n_in,
                              void* d_out, int out_size) {
    const float* x  = (const float*)d_in[0];   // (1,512,32,32)
    const float* w1 = (const float*)d_in[1];   // (32,512)
    const float* b1 = (const float*)d_in[2];   // (32)
    const float* w2 = (const float*)d_in[3];   // (512,32)
    const float* b2 = (const float*)d_in[4];   // (512)
    const float* dw = (const float*)d_in[5];   // (512,1024)
    float* out = (float*)d_out;                // (1,512,32,32) fp32

    k_mean_initA<<<513, 256>>>(x);
    k_mlp<<<1, 1024>>>(w1, b1, w2, b2);
    k_gauss_trans<<<1024, 256>>>(x);
    k_csa<<<1024, 256>>>();
    k_gemm<<<dim3(16, 8), 256>>>(dw, out);
    k_norm<<<512, 256>>>(out);
}

// round 6
// speedup vs baseline: 1.5708x; 1.0234x over previous
#include <cuda_runtime.h>
#include <math.h>

#define NC 512
#define NPIX 1024

// ---------------- scratch (no allocations allowed) ----------------
__device__ float g_y[NC];                 // channel means
__device__ float g_s[NC];                 // SE scales
__device__ float g_A[32 * 32];            // row-stochastic gaussian matrix A[i][x]
__device__ float g_f0t[NPIX * NC];        // f0 transposed: [pix][ch]
__device__ float g_sigt[NPIX * NC];       // sigmoid(f0): [pix][ch]
__device__ float g_cat[2 * NPIX * NC];    // [0..512K): gus flat, [512K..1M): csa flat

// ---------------- 1. per-channel mean (blocks 0..511) + gaussian matrix A (block 512) ----------------
__global__ void k_mean_initA(const float* __restrict__ x) {
    int t = threadIdx.x;
    if (blockIdx.x < 512) {
        int c = blockIdx.x;
        float4 v = ((const float4*)(x + c * 1024))[t];
        float s = v.x + v.y + v.z + v.w;
        #pragma unroll
        for (int o = 16; o; o >>= 1) s += __shfl_down_sync(0xffffffffu, s, o);
        __shared__ float ws[8];
        if ((t & 31) == 0) ws[t >> 5] = s;
        __syncthreads();
        if (t == 0) {
            float tot = 0.f;
            #pragma unroll
            for (int i = 0; i < 8; i++) tot += ws[i];
            g_y[c] = tot * (1.f / 1024.f);
        }
    } else {
        __shared__ double srow[32];
        if (t < 32) {
            double s = 0.0;
            for (int xx = 0; xx < 32; xx++) {
                double d = (double)(xx - t);
                s += exp(-d * d / 4.5);
            }
            srow[t] = s;
        }
        __syncthreads();
        for (int idx = t; idx < 1024; idx += 256) {
            int i = idx >> 5, xx = idx & 31;
            double d = (double)(xx - i);
            g_A[idx] = (float)(exp(-d * d / 4.5) / srow[i]);
        }
    }
}

// ---------------- 2. SE MLP: 512 -> 32 (relu) -> 512 (sigmoid) ----------------
__global__ void k_mlp(const float* __restrict__ w1, const float* __restrict__ b1,
                      const float* __restrict__ w2, const float* __restrict__ b2) {
    __shared__ float sy[512];
    __shared__ float sh[32];
    int t = threadIdx.x;
    if (t < 512) sy[t] = g_y[t];
    __syncthreads();
    int r = t >> 5, lane = t & 31;   // 32 warps, one per hidden unit
    float a = 0.f;
    for (int c = lane; c < 512; c += 32) a += sy[c] * w1[r * 512 + c];
    #pragma unroll
    for (int o = 16; o; o >>= 1) a += __shfl_down_sync(0xffffffffu, a, o);
    if (lane == 0) sh[r] = fmaxf(a + b1[r], 0.f);
    __syncthreads();
    if (t < 512) {
        float acc = b2[t];
        #pragma unroll
        for (int rr = 0; rr < 32; rr++) acc += sh[rr] * w2[t * 32 + rr];
        g_s[t] = 1.f / (1.f + expf(-acc));
    }
}

// ---------------- 3. fused: gaussian pooling (blocks 0..511) + scale/transpose/sigmoid (512..1023) ----------------
__global__ void k_gauss_trans(const float* __restrict__ x) {
    __shared__ float sbuf[4096];
    int t = threadIdx.x;
    if (blockIdx.x < 512) {
        float* F   = sbuf;
        float* T   = sbuf + 1024;
        float* sA  = sbuf + 2048;
        float* sAt = sbuf + 3072;
        int c = blockIdx.x;
        float s = g_s[c];
        for (int i = t; i < 1024; i += 256) {
            F[i] = x[c * 1024 + i] * s;
            float a = g_A[i];
            sA[i] = a;                                // sA[k*32+y]  = A[k][y]
            sAt[(i & 31) * 32 + (i >> 5)] = a;        // sAt[y*32+k] = A[k][y]
        }
        __syncthreads();
        for (int idx = t; idx < 1024; idx += 256) {   // T[x][k] = sum_y A[k][y]*F[x][y]
            int xx = idx >> 5, k = idx & 31;
            float acc = 0.f;
            #pragma unroll
            for (int y = 0; y < 32; y++) acc += sAt[y * 32 + k] * F[xx * 32 + y];
            T[idx] = acc;
        }
        __syncthreads();
        for (int idx = t; idx < 1024; idx += 256) {   // B[i][k] = sum_x A[i][x]*T[x][k]
            int i = idx >> 5, k = idx & 31;
            float acc = 0.f;
            #pragma unroll
            for (int xx = 0; xx < 32; xx++) acc += sA[i * 32 + xx] * T[xx * 32 + k];
            g_cat[idx * 512 + c] = acc;
        }
    } else {
        float (*tile)[33] = (float(*)[33])sbuf;
        int bid = blockIdx.x - 512;
        int p0 = (bid & 31) * 32, c0 = (bid >> 5) * 32;
        int tx = t & 31, ty = t >> 5;
        #pragma unroll
        for (int j = 0; j < 4; j++) {
            int ch = c0 + ty + j * 8;
            tile[ty + j * 8][tx] = x[ch * 1024 + p0 + tx] * g_s[ch];
        }
        __syncthreads();
        #pragma unroll
        for (int j = 0; j < 4; j++) {
            int p = p0 + ty + j * 8;
            float v = tile[tx][ty + j * 8];
            g_f0t[p * 512 + c0 + tx] = v;
            g_sigt[p * 512 + c0 + tx] = 1.f / (1.f + expf(-v));
        }
    }
}

// ---------------- 4. 3x3 patch-correlation attention: constant-offset addressing ----------------
__global__ void k_csa() {
    int pix = blockIdx.x, pi = pix >> 5, pj = pix & 31;
    int t = threadIdx.x;
    int base = pix * 512 + t;          // channels c0=t, c1=t+256
    __shared__ float wsum[8][9];
    __shared__ float sa[9];

    float sc0 = g_sigt[base];
    float sc1 = g_sigt[base + 256];

    bool okU = pi > 0, okD = pi < 31, okL = pj > 0, okR = pj < 31;
    bool ok[9];
    ok[0] = okU && okL; ok[1] = okU; ok[2] = okU && okR;
    ok[3] = okL;        ok[4] = true; ok[5] = okR;
    ok[6] = okD && okL; ok[7] = okD; ok[8] = okD && okR;
    const int off[9] = { -33*512, -32*512, -31*512, -1*512, 0, 1*512, 31*512, 32*512, 33*512 };

    float acc[9];
    #pragma unroll
    for (int uv = 0; uv < 9; uv++) {
        acc[uv] = ok[uv]
            ? sc0 * g_sigt[base + off[uv]] + sc1 * g_sigt[base + off[uv] + 256]
            : 0.f;
    }
    #pragma unroll
    for (int uv = 0; uv < 9; uv++)
        #pragma unroll
        for (int o = 16; o; o >>= 1) acc[uv] += __shfl_down_sync(0xffffffffu, acc[uv], o);
    if ((t & 31) == 0) {
        #pragma unroll
        for (int uv = 0; uv < 9; uv++) wsum[t >> 5][uv] = acc[uv];
    }
    __syncthreads();
    // distributed softmax over 9 taps on warp 0
    if (t < 32) {
        float v = -1e30f;
        if (t < 9) {
            float s2 = 0.f;
            #pragma unroll
            for (int w = 0; w < 8; w++) s2 += wsum[w][t];
            v = s2 * (1.f / 512.f);
        }
        float m = v;
        #pragma unroll
        for (int o = 16; o; o >>= 1) m = fmaxf(m, __shfl_xor_sync(0xffffffffu, m, o));
        float e = (t < 9) ? expf(v - m) : 0.f;
        float tot = e;
        #pragma unroll
        for (int o = 16; o; o >>= 1) tot += __shfl_xor_sync(0xffffffffu, tot, o);
        if (t < 9) sa[t] = e / tot;
    }
    __syncthreads();

    float o0 = 0.f, o1 = 0.f;
    #pragma unroll
    for (int uv = 0; uv < 9; uv++) {
        if (ok[uv]) {
            float a = sa[uv];
            o0 += a * g_f0t[base + off[uv]];
            o1 += a * g_f0t[base + off[uv] + 256];
        }
    }
    g_cat[524288 + base] = o0;
    g_cat[524288 + base + 256] = o1;
}

// ---------------- 5. down GEMM: cp.async 2-stage double-buffered FFMA ----------------
// z[512,1024] = W[512,1024] @ cat[1024,1024]; 64x64 block tile, 256 thr, 4x4 micro.
// A stored [m][k] (cp.async can't transpose); consumed as float4-along-k fragments.
#define LDK 36   // A tile row stride in floats (144B, 16B-aligned, conflict-skewed)

#define CPA16(sm, g) asm volatile("cp.async.ca.shared.global [%0], [%1], 16;" :: "r"(sm), "l"(g))
#define CPA_COMMIT()  asm volatile("cp.async.commit_group;" ::: "memory")
#define CPA_WAIT0()   asm volatile("cp.async.wait_group 0;" ::: "memory")

__global__ void __launch_bounds__(256) k_gemm(const float* __restrict__ Wd,
                                              float* __restrict__ out) {
    __shared__ float As[2][64 * LDK];   // [stage][m][k]
    __shared__ float Bs[2][32 * 64];    // [stage][k][n]
    int t = threadIdx.x;
    int tx = t & 15, ty = t >> 4;
    int m0 = blockIdx.y * 64, n0 = blockIdx.x * 64;

    // A tile: 64 rows x 32 k = 512 float4; thread handles e=t and e=t+256
    int ar0 = t >> 3,         ak0 = (t & 7) * 4;
    int ar1 = (t + 256) >> 3, ak1 = (t & 7) * 4;
    // B tile: 32 k x 64 n = 512 float4
    int bk0 = t >> 4,         bn0 = (t & 15) * 4;
    int bk1 = (t + 256) >> 4, bn1 = (t & 15) * 4;

    unsigned aSm[2][2], bSm[2][2];
    #pragma unroll
    for (int s = 0; s < 2; s++) {
        unsigned ab = (unsigned)__cvta_generic_to_shared(&As[s][0]);
        unsigned bb = (unsigned)__cvta_generic_to_shared(&Bs[s][0]);
        aSm[s][0] = ab + (ar0 * LDK + ak0) * 4;
        aSm[s][1] = ab + (ar1 * LDK + ak1) * 4;
        bSm[s][0] = bb + (bk0 * 64 + bn0) * 4;
        bSm[s][1] = bb + (bk1 * 64 + bn1) * 4;
    }
    const float* aG0 = Wd + (m0 + ar0) * 1024 + ak0;
    const float* aG1 = Wd + (m0 + ar1) * 1024 + ak1;
    const float* bG0 = g_cat + bk0 * 1024 + n0 + bn0;
    const float* bG1 = g_cat + bk1 * 1024 + n0 + bn1;

    // prologue: stage 0, k0 = 0
    CPA16(aSm[0][0], aG0);
    CPA16(aSm[0][1], aG1);
    CPA16(bSm[0][0], bG0);
    CPA16(bSm[0][1], bG1);
    CPA_COMMIT();

    float acc[4][4] = {};

    #pragma unroll 1
    for (int kt = 0; kt < 32; kt++) {
        CPA_WAIT0();
        __syncthreads();   // all copies visible; all threads done reading the other stage
        if (kt < 31) {
            int s = (kt + 1) & 1, ko = (kt + 1) * 32;
            CPA16(aSm[s][0], aG0 + ko);
            CPA16(aSm[s][1], aG1 + ko);
            CPA16(bSm[s][0], bG0 + ko * 1024);
            CPA16(bSm[s][1], bG1 + ko * 1024);
            CPA_COMMIT();
        }
        const float* A = &As[kt & 1][0];
        const float* B = &Bs[kt & 1][0];
        #pragma unroll
        for (int k = 0; k < 32; k += 4) {
            float4 b0 = *(const float4*)&B[(k + 0) * 64 + tx * 4];
            float4 b1 = *(const float4*)&B[(k + 1) * 64 + tx * 4];
            float4 b2 = *(const float4*)&B[(k + 2) * 64 + tx * 4];
            float4 b3 = *(const float4*)&B[(k + 3) * 64 + tx * 4];
            #pragma unroll
            for (int i = 0; i < 4; i++) {
                float4 a = *(const float4*)&A[(ty * 4 + i) * LDK + k];
                acc[i][0] += a.x * b0.x; acc[i][1] += a.x * b0.y; acc[i][2] += a.x * b0.z; acc[i][3] += a.x * b0.w;
                acc[i][0] += a.y * b1.x; acc[i][1] += a.y * b1.y; acc[i][2] += a.y * b1.z; acc[i][3] += a.y * b1.w;
                acc[i][0] += a.z * b2.x; acc[i][1] += a.z * b2.y; acc[i][2] += a.z * b2.z; acc[i][3] += a.z * b2.w;
                acc[i][0] += a.w * b3.x; acc[i][1] += a.w * b3.y; acc[i][2] += a.w * b3.z; acc[i][3] += a.w * b3.w;
            }
        }
    }
    #pragma unroll
    for (int i = 0; i < 4; i++) {
        float4 r = make_float4(acc[i][0], acc[i][1], acc[i][2], acc[i][3]);
        *(float4*)(out + (m0 + ty * 4 + i) * 1024 + n0 + tx * 4) = r;
    }
}

// ---------------- 6. instance norm + leaky relu (in place) ----------------
__global__ void k_norm(float* __restrict__ out) {
    int o = blockIdx.x, t = threadIdx.x;
    float4* row = (float4*)(out + o * 1024);
    float4 v = row[t];
    float s = v.x + v.y + v.z + v.w;
    float ss = v.x * v.x + v.y * v.y + v.z * v.z + v.w * v.w;
    #pragma unroll
    for (int off = 16; off; off >>= 1) {
        s  += __shfl_down_sync(0xffffffffu, s, off);
        ss += __shfl_down_sync(0xffffffffu, ss, off);
    }
    __shared__ float w1s[8], w2s[8];
    __shared__ float smean, sinv;
    if ((t & 31) == 0) { w1s[t >> 5] = s; w2s[t >> 5] = ss; }
    __syncthreads();
    if (t == 0) {
        float ts = 0.f, tss = 0.f;
        #pragma unroll
        for (int i = 0; i < 8; i++) { ts += w1s[i]; tss += w2s[i]; }
        float mu = ts * (1.f / 1024.f);
        float var = tss * (1.f / 1024.f) - mu * mu;
        smean = mu;
        sinv = 1.f / sqrtf(var + 1e-5f);
    }
    __syncthreads();
    float mu = smean, inv = sinv;
    float a;
    a = (v.x - mu) * inv; v.x = a >= 0.f ? a : 0.2f * a;
    a = (v.y - mu) * inv; v.y = a >= 0.f ? a : 0.2f * a;
    a = (v.z - mu) * inv; v.z = a >= 0.f ? a : 0.2f * a;
    a = (v.w - mu) * inv; v.w = a >= 0.f ? a : 0.2f * a;
    row[t] = v;
}

// ---------------- launch ----------------
extern "C" void kernel_launch(void* const* d_in, const int* in_sizes, int n_in,
                              void* d_out, int out_size) {
    const float* x  = (const float*)d_in[0];   // (1,512,32,32)
    const float* w1 = (const float*)d_in[1];   // (32,512)
    const float* b1 = (const float*)d_in[2];   // (32)
    const float* w2 = (const float*)d_in[3];   // (512,32)
    const float* b2 = (const float*)d_in[4];   // (512)
    const float* dw = (const float*)d_in[5];   // (512,1024)
    float* out = (float*)d_out;                // (1,512,32,32) fp32

    k_mean_initA<<<513, 256>>>(x);
    k_mlp<<<1, 1024>>>(w1, b1, w2, b2);
    k_gauss_trans<<<1024, 256>>>(x);
    k_csa<<<1024, 256>>>();
    k_gemm<<<dim3(16, 8), 256>>>(dw, out);
    k_norm<<<512, 256>>>(out);
}

// round 7
// speedup vs baseline: 1.6398x; 1.0439x over previous
#include <cuda_runtime.h>
#include <math.h>

#define NC 512
#define NPIX 1024

// ---------------- scratch (no allocations allowed) ----------------
__device__ float g_y[NC];                 // channel means
__device__ float g_s[NC];                 // SE scales
__device__ float g_A[32 * 32];            // row-stochastic gaussian matrix A[i][x]
__device__ float g_f0t[NPIX * NC];        // f0 transposed: [pix][ch]
__device__ float g_sigt[NPIX * NC];       // sigmoid(f0): [pix][ch]
__device__ float g_cat[2 * NPIX * NC];    // [0..512K): gus flat, [512K..1M): csa flat
__device__ float g_z1[NC * NPIX];         // split-K half-1 partial

// ---------------- 1. per-channel mean (blocks 0..511) + gaussian matrix A (block 512) ----------------
__global__ void k_mean_initA(const float* __restrict__ x) {
    int t = threadIdx.x;
    if (blockIdx.x < 512) {
        int c = blockIdx.x;
        float4 v = ((const float4*)(x + c * 1024))[t];
        float s = v.x + v.y + v.z + v.w;
        #pragma unroll
        for (int o = 16; o; o >>= 1) s += __shfl_down_sync(0xffffffffu, s, o);
        __shared__ float ws[8];
        if ((t & 31) == 0) ws[t >> 5] = s;
        __syncthreads();
        if (t == 0) {
            float tot = 0.f;
            #pragma unroll
            for (int i = 0; i < 8; i++) tot += ws[i];
            g_y[c] = tot * (1.f / 1024.f);
        }
    } else {
        __shared__ double srow[32];
        if (t < 32) {
            double s = 0.0;
            for (int xx = 0; xx < 32; xx++) {
                double d = (double)(xx - t);
                s += exp(-d * d / 4.5);
            }
            srow[t] = s;
        }
        __syncthreads();
        for (int idx = t; idx < 1024; idx += 256) {
            int i = idx >> 5, xx = idx & 31;
            double d = (double)(xx - i);
            g_A[idx] = (float)(exp(-d * d / 4.5) / srow[i]);
        }
    }
}

// ---------------- 2. SE MLP: 512 -> 32 (relu) -> 512 (sigmoid) ----------------
__global__ void k_mlp(const float* __restrict__ w1, const float* __restrict__ b1,
                      const float* __restrict__ w2, const float* __restrict__ b2) {
    __shared__ float sy[512];
    __shared__ float sh[32];
    int t = threadIdx.x;
    if (t < 512) sy[t] = g_y[t];
    __syncthreads();
    int r = t >> 5, lane = t & 31;   // 32 warps, one per hidden unit
    float a = 0.f;
    for (int c = lane; c < 512; c += 32) a += sy[c] * w1[r * 512 + c];
    #pragma unroll
    for (int o = 16; o; o >>= 1) a += __shfl_down_sync(0xffffffffu, a, o);
    if (lane == 0) sh[r] = fmaxf(a + b1[r], 0.f);
    __syncthreads();
    if (t < 512) {
        float acc = b2[t];
        #pragma unroll
        for (int rr = 0; rr < 32; rr++) acc += sh[rr] * w2[t * 32 + rr];
        g_s[t] = 1.f / (1.f + expf(-acc));
    }
}

// ---------------- 3. fused: gaussian pooling (blocks 0..511) + scale/transpose/sigmoid (512..1023) ----------------
__global__ void k_gauss_trans(const float* __restrict__ x) {
    __shared__ float sbuf[4096];
    int t = threadIdx.x;
    if (blockIdx.x < 512) {
        float* F   = sbuf;
        float* T   = sbuf + 1024;
        float* sA  = sbuf + 2048;
        float* sAt = sbuf + 3072;
        int c = blockIdx.x;
        float s = g_s[c];
        for (int i = t; i < 1024; i += 256) {
            F[i] = x[c * 1024 + i] * s;
            float a = g_A[i];
            sA[i] = a;                                // sA[k*32+y]  = A[k][y]
            sAt[(i & 31) * 32 + (i >> 5)] = a;        // sAt[y*32+k] = A[k][y]
        }
        __syncthreads();
        for (int idx = t; idx < 1024; idx += 256) {   // T[x][k] = sum_y A[k][y]*F[x][y]
            int xx = idx >> 5, k = idx & 31;
            float acc = 0.f;
            #pragma unroll
            for (int y = 0; y < 32; y++) acc += sAt[y * 32 + k] * F[xx * 32 + y];
            T[idx] = acc;
        }
        __syncthreads();
        for (int idx = t; idx < 1024; idx += 256) {   // B[i][k] = sum_x A[i][x]*T[x][k]
            int i = idx >> 5, k = idx & 31;
            float acc = 0.f;
            #pragma unroll
            for (int xx = 0; xx < 32; xx++) acc += sA[i * 32 + xx] * T[xx * 32 + k];
            g_cat[idx * 512 + c] = acc;
        }
    } else {
        float (*tile)[33] = (float(*)[33])sbuf;
        int bid = blockIdx.x - 512;
        int p0 = (bid & 31) * 32, c0 = (bid >> 5) * 32;
        int tx = t & 31, ty = t >> 5;
        #pragma unroll
        for (int j = 0; j < 4; j++) {
            int ch = c0 + ty + j * 8;
            tile[ty + j * 8][tx] = x[ch * 1024 + p0 + tx] * g_s[ch];
        }
        __syncthreads();
        #pragma unroll
        for (int j = 0; j < 4; j++) {
            int p = p0 + ty + j * 8;
            float v = tile[tx][ty + j * 8];
            g_f0t[p * 512 + c0 + tx] = v;
            g_sigt[p * 512 + c0 + tx] = 1.f / (1.f + expf(-v));
        }
    }
}

// ---------------- 4. 3x3 patch-correlation attention ----------------
__global__ void k_csa() {
    int pix = blockIdx.x, pi = pix >> 5, pj = pix & 31;
    int t = threadIdx.x;
    int base = pix * 512 + t;          // channels c0=t, c1=t+256
    __shared__ float wsum[8][9];
    __shared__ float sa[9];

    float sc0 = g_sigt[base];
    float sc1 = g_sigt[base + 256];

    bool okU = pi > 0, okD = pi < 31, okL = pj > 0, okR = pj < 31;
    bool ok[9];
    ok[0] = okU && okL; ok[1] = okU; ok[2] = okU && okR;
    ok[3] = okL;        ok[4] = true; ok[5] = okR;
    ok[6] = okD && okL; ok[7] = okD; ok[8] = okD && okR;
    const int off[9] = { -33*512, -32*512, -31*512, -1*512, 0, 1*512, 31*512, 32*512, 33*512 };

    float acc[9];
    #pragma unroll
    for (int uv = 0; uv < 9; uv++) {
        acc[uv] = ok[uv]
            ? sc0 * g_sigt[base + off[uv]] + sc1 * g_sigt[base + off[uv] + 256]
            : 0.f;
    }
    // prefetch the f0t lines we'll gather after the softmax (hides L2 latency, no regs)
    #pragma unroll
    for (int uv = 0; uv < 9; uv++) {
        if (ok[uv]) {
            asm volatile("prefetch.global.L1 [%0];" :: "l"(g_f0t + base + off[uv]));
            asm volatile("prefetch.global.L1 [%0];" :: "l"(g_f0t + base + off[uv] + 256));
        }
    }
    #pragma unroll
    for (int uv = 0; uv < 9; uv++)
        #pragma unroll
        for (int o = 16; o; o >>= 1) acc[uv] += __shfl_down_sync(0xffffffffu, acc[uv], o);
    if ((t & 31) == 0) {
        #pragma unroll
        for (int uv = 0; uv < 9; uv++) wsum[t >> 5][uv] = acc[uv];
    }
    __syncthreads();
    // distributed softmax over 9 taps on warp 0
    if (t < 32) {
        float v = -1e30f;
        if (t < 9) {
            float s2 = 0.f;
            #pragma unroll
            for (int w = 0; w < 8; w++) s2 += wsum[w][t];
            v = s2 * (1.f / 512.f);
        }
        float m = v;
        #pragma unroll
        for (int o = 16; o; o >>= 1) m = fmaxf(m, __shfl_xor_sync(0xffffffffu, m, o));
        float e = (t < 9) ? expf(v - m) : 0.f;
        float tot = e;
        #pragma unroll
        for (int o = 16; o; o >>= 1) tot += __shfl_xor_sync(0xffffffffu, tot, o);
        if (t < 9) sa[t] = e / tot;
    }
    __syncthreads();

    float o0 = 0.f, o1 = 0.f;
    #pragma unroll
    for (int uv = 0; uv < 9; uv++) {
        if (ok[uv]) {
            float a = sa[uv];
            o0 += a * g_f0t[base + off[uv]];
            o1 += a * g_f0t[base + off[uv] + 256];
        }
    }
    g_cat[524288 + base] = o0;
    g_cat[524288 + base + 256] = o1;
}

// ---------------- 5. down GEMM: split-K=2, cp.async 2-stage, FFMA ----------------
// z[512,1024] = W[512,1024] @ cat[1024,1024]; 64x64 tiles, K split in halves.
// Half 0 -> out, half 1 -> g_z1; summed in k_norm. 256 blocks => ~2 blocks/SM.
#define LDK 36

#define CPA16(sm, g) asm volatile("cp.async.ca.shared.global [%0], [%1], 16;" :: "r"(sm), "l"(g))
#define CPA_COMMIT()  asm volatile("cp.async.commit_group;" ::: "memory")
#define CPA_WAIT0()   asm volatile("cp.async.wait_group 0;" ::: "memory")

__global__ void __launch_bounds__(256) k_gemm(const float* __restrict__ Wd,
                                              float* __restrict__ out) {
    __shared__ float As[2][64 * LDK];   // [stage][m][k]
    __shared__ float Bs[2][32 * 64];    // [stage][k][n]
    int t = threadIdx.x;
    int tx = t & 15, ty = t >> 4;
    int m0 = blockIdx.y * 64, n0 = blockIdx.x * 64;
    int kbase = blockIdx.z * 512;       // split-K half

    int ar0 = t >> 3,         ak0 = (t & 7) * 4;
    int ar1 = (t + 256) >> 3, ak1 = (t & 7) * 4;
    int bk0 = t >> 4,         bn0 = (t & 15) * 4;
    int bk1 = (t + 256) >> 4, bn1 = (t & 15) * 4;

    unsigned aSm[2][2], bSm[2][2];
    #pragma unroll
    for (int s = 0; s < 2; s++) {
        unsigned ab = (unsigned)__cvta_generic_to_shared(&As[s][0]);
        unsigned bb = (unsigned)__cvta_generic_to_shared(&Bs[s][0]);
        aSm[s][0] = ab + (ar0 * LDK + ak0) * 4;
        aSm[s][1] = ab + (ar1 * LDK + ak1) * 4;
        bSm[s][0] = bb + (bk0 * 64 + bn0) * 4;
        bSm[s][1] = bb + (bk1 * 64 + bn1) * 4;
    }
    const float* aG0 = Wd + (m0 + ar0) * 1024 + kbase + ak0;
    const float* aG1 = Wd + (m0 + ar1) * 1024 + kbase + ak1;
    const float* bG0 = g_cat + (kbase + bk0) * 1024 + n0 + bn0;
    const float* bG1 = g_cat + (kbase + bk1) * 1024 + n0 + bn1;

    CPA16(aSm[0][0], aG0);
    CPA16(aSm[0][1], aG1);
    CPA16(bSm[0][0], bG0);
    CPA16(bSm[0][1], bG1);
    CPA_COMMIT();

    float acc[4][4] = {};

    #pragma unroll 1
    for (int kt = 0; kt < 16; kt++) {
        CPA_WAIT0();
        __syncthreads();
        if (kt < 15) {
            int s = (kt + 1) & 1, ko = (kt + 1) * 32;
            CPA16(aSm[s][0], aG0 + ko);
            CPA16(aSm[s][1], aG1 + ko);
            CPA16(bSm[s][0], bG0 + ko * 1024);
            CPA16(bSm[s][1], bG1 + ko * 1024);
            CPA_COMMIT();
        }
        const float* A = &As[kt & 1][0];
        const float* B = &Bs[kt & 1][0];
        #pragma unroll
        for (int k = 0; k < 32; k += 4) {
            float4 b0 = *(const float4*)&B[(k + 0) * 64 + tx * 4];
            float4 b1 = *(const float4*)&B[(k + 1) * 64 + tx * 4];
            float4 b2 = *(const float4*)&B[(k + 2) * 64 + tx * 4];
            float4 b3 = *(const float4*)&B[(k + 3) * 64 + tx * 4];
            #pragma unroll
            for (int i = 0; i < 4; i++) {
                float4 a = *(const float4*)&A[(ty * 4 + i) * LDK + k];
                acc[i][0] += a.x * b0.x; acc[i][1] += a.x * b0.y; acc[i][2] += a.x * b0.z; acc[i][3] += a.x * b0.w;
                acc[i][0] += a.y * b1.x; acc[i][1] += a.y * b1.y; acc[i][2] += a.y * b1.z; acc[i][3] += a.y * b1.w;
                acc[i][0] += a.z * b2.x; acc[i][1] += a.z * b2.y; acc[i][2] += a.z * b2.z; acc[i][3] += a.z * b2.w;
                acc[i][0] += a.w * b3.x; acc[i][1] += a.w * b3.y; acc[i][2] += a.w * b3.z; acc[i][3] += a.w * b3.w;
            }
        }
    }
    float* dst = blockIdx.z ? g_z1 : out;
    #pragma unroll
    for (int i = 0; i < 4; i++) {
        float4 r = make_float4(acc[i][0], acc[i][1], acc[i][2], acc[i][3]);
        *(float4*)(dst + (m0 + ty * 4 + i) * 1024 + n0 + tx * 4) = r;
    }
}

// ---------------- 6. split-K sum + instance norm + leaky relu ----------------
__global__ void k_norm(float* __restrict__ out) {
    int o = blockIdx.x, t = threadIdx.x;
    float4* row = (float4*)(out + o * 1024);
    const float4* row1 = (const float4*)(g_z1 + o * 1024);
    float4 v = row[t];
    float4 v1 = row1[t];
    v.x += v1.x; v.y += v1.y; v.z += v1.z; v.w += v1.w;
    float s = v.x + v.y + v.z + v.w;
    float ss = v.x * v.x + v.y * v.y + v.z * v.z + v.w * v.w;
    #pragma unroll
    for (int off = 16; off; off >>= 1) {
        s  += __shfl_down_sync(0xffffffffu, s, off);
        ss += __shfl_down_sync(0xffffffffu, ss, off);
    }
    __shared__ float w1s[8], w2s[8];
    __shared__ float smean, sinv;
    if ((t & 31) == 0) { w1s[t >> 5] = s; w2s[t >> 5] = ss; }
    __syncthreads();
    if (t == 0) {
        float ts = 0.f, tss = 0.f;
        #pragma unroll
        for (int i = 0; i < 8; i++) { ts += w1s[i]; tss += w2s[i]; }
        float mu = ts * (1.f / 1024.f);
        float var = tss * (1.f / 1024.f) - mu * mu;
        smean = mu;
        sinv = 1.f / sqrtf(var + 1e-5f);
    }
    __syncthreads();
    float mu = smean, inv = sinv;
    float a;
    a = (v.x - mu) * inv; v.x = a >= 0.f ? a : 0.2f * a;
    a = (v.y - mu) * inv; v.y = a >= 0.f ? a : 0.2f * a;
    a = (v.z - mu) * inv; v.z = a >= 0.f ? a : 0.2f * a;
    a = (v.w - mu) * inv; v.w = a >= 0.f ? a : 0.2f * a;
    row[t] = v;
}

// ---------------- launch ----------------
extern "C" void kernel_launch(void* const* d_in, const int* in_sizes, int n_in,
                              void* d_out, int out_size) {
    const float* x  = (const float*)d_in[0];   // (1,512,32,32)
    const float* w1 = (const float*)d_in[1];   // (32,512)
    const float* b1 = (const float*)d_in[2];   // (32)
    const float* w2 = (const float*)d_in[3];   // (512,32)
    const float* b2 = (const float*)d_in[4];   // (512)
    const float* dw = (const float*)d_in[5];   // (512,1024)
    float* out = (float*)d_out;                // (1,512,32,32) fp32

    k_mean_initA<<<513, 256>>>(x);
    k_mlp<<<1, 1024>>>(w1, b1, w2, b2);
    k_gauss_trans<<<1024, 256>>>(x);
    k_csa<<<1024, 256>>>();
    k_gemm<<<dim3(16, 8, 2), 256>>>(dw, out);
    k_norm<<<512, 256>>>(out);
}

// round 10
// speedup vs baseline: 1.8325x; 1.1176x over previous
#include <cuda_runtime.h>
#include <cuda_fp16.h>
#include <stdint.h>
#include <math.h>

#define NC 512
#define NPIX 1024

// ---------------- scratch (no allocations allowed) ----------------
__device__ float g_y[NC];                   // channel means
__device__ float g_s[NC];                   // SE scales
__device__ float g_A[32 * 32];              // gaussian matrix A[i][x]
__device__ float g_f0t[NPIX * NC];          // f0 transposed: [pix][ch]
__device__ float g_sigt[NPIX * NC];         // sigmoid(f0): [pix][ch]
__device__ __half g_Wh[NC * 1024];          // W fp16 hi, [o][i] k-major
__device__ __half g_Wl[NC * 1024];          // W fp16 residual
__device__ __half g_ch[1024 * 1024];        // cat^T fp16 hi: [q pix][i] k-major
__device__ __half g_cl[1024 * 1024];        // cat^T fp16 residual

// ---------------- helpers ----------------
__device__ __forceinline__ uint32_t smem_u32(const void* p) {
    uint32_t a;
    asm("{ .reg .u64 t; cvta.to.shared.u64 t, %1; cvt.u32.u64 %0, t; }" : "=r"(a) : "l"(p));
    return a;
}
#define CPA16(sm, g) asm volatile("cp.async.ca.shared.global [%0], [%1], 16;" :: "r"(sm), "l"(g))
#define CPA_COMMIT()  asm volatile("cp.async.commit_group;" ::: "memory")
#define CPA_WAIT0()   asm volatile("cp.async.wait_group 0;" ::: "memory")

#define LDMX4(r, a) \
    asm volatile("ldmatrix.sync.aligned.m8n8.x4.shared.b16 {%0,%1,%2,%3}, [%4];" \
                 : "=r"((r)[0]), "=r"((r)[1]), "=r"((r)[2]), "=r"((r)[3]) : "r"(a))

#define MMA16(d, a, b0v, b1v) \
    asm volatile("mma.sync.aligned.m16n8k16.row.col.f32.f16.f16.f32 " \
                 "{%0,%1,%2,%3},{%4,%5,%6,%7},{%8,%9},{%0,%1,%2,%3};" \
                 : "+f"((d)[0]), "+f"((d)[1]), "+f"((d)[2]), "+f"((d)[3]) \
                 : "r"((a)[0]), "r"((a)[1]), "r"((a)[2]), "r"((a)[3]), "r"(b0v), "r"(b1v))

__device__ __forceinline__ void split_h(float f, __half& h, __half& l) {
    h = __float2half_rn(f);
    l = __float2half_rn(f - __half2float(h));
}

// ---------------- 1. per-channel mean (0..511) + gaussian A (512) + W fp16-split (513..1024) ----------------
__global__ void k_mean_initA(const float* __restrict__ x, const float* __restrict__ dw) {
    int t = threadIdx.x;
    if (blockIdx.x < 512) {
        int c = blockIdx.x;
        float4 v = ((const float4*)(x + c * 1024))[t];
        float s = v.x + v.y + v.z + v.w;
        #pragma unroll
        for (int o = 16; o; o >>= 1) s += __shfl_down_sync(0xffffffffu, s, o);
        __shared__ float ws[8];
        if ((t & 31) == 0) ws[t >> 5] = s;
        __syncthreads();
        if (t == 0) {
            float tot = 0.f;
            #pragma unroll
            for (int i = 0; i < 8; i++) tot += ws[i];
            g_y[c] = tot * (1.f / 1024.f);
        }
    } else if (blockIdx.x == 512) {
        __shared__ double srow[32];
        if (t < 32) {
            double s = 0.0;
            for (int xx = 0; xx < 32; xx++) {
                double d = (double)(xx - t);
                s += exp(-d * d / 4.5);
            }
            srow[t] = s;
        }
        __syncthreads();
        for (int idx = t; idx < 1024; idx += 256) {
            int i = idx >> 5, xx = idx & 31;
            double d = (double)(xx - i);
            g_A[idx] = (float)(exp(-d * d / 4.5) / srow[i]);
        }
    } else {
        int row = blockIdx.x - 513;   // 0..511
        #pragma unroll
        for (int j = 0; j < 4; j++) {
            int idx = row * 1024 + t + j * 256;
            __half h, l;
            split_h(dw[idx], h, l);
            g_Wh[idx] = h;
            g_Wl[idx] = l;
        }
    }
}

// ---------------- 2. SE MLP: 512 -> 32 (relu) -> 512 (sigmoid) ----------------
__global__ void k_mlp(const float* __restrict__ w1, const float* __restrict__ b1,
                      const float* __restrict__ w2, const float* __restrict__ b2) {
    __shared__ float sy[512];
    __shared__ float sh[32];
    int t = threadIdx.x;
    if (t < 512) sy[t] = g_y[t];
    __syncthreads();
    int r = t >> 5, lane = t & 31;
    float a = 0.f;
    for (int c = lane; c < 512; c += 32) a += sy[c] * w1[r * 512 + c];
    #pragma unroll
    for (int o = 16; o; o >>= 1) a += __shfl_down_sync(0xffffffffu, a, o);
    if (lane == 0) sh[r] = fmaxf(a + b1[r], 0.f);
    __syncthreads();
    if (t < 512) {
        float acc = b2[t];
        #pragma unroll
        for (int rr = 0; rr < 32; rr++) acc += sh[rr] * w2[t * 32 + rr];
        g_s[t] = 1.f / (1.f + expf(-acc));
    }
}

// ---------------- 3. fused: gaussian pooling (0..511) + scale/transpose/sigmoid (512..1023) ----------------
__global__ void k_gauss_trans(const float* __restrict__ x) {
    __shared__ float sbuf[4096];
    int t = threadIdx.x;
    if (blockIdx.x < 512) {
        float* F   = sbuf;
        float* T   = sbuf + 1024;
        float* sA  = sbuf + 2048;
        float* sAt = sbuf + 3072;
        int c = blockIdx.x;
        float s = g_s[c];
        for (int i = t; i < 1024; i += 256) {
            F[i] = x[c * 1024 + i] * s;
            float a = g_A[i];
            sA[i] = a;
            sAt[(i & 31) * 32 + (i >> 5)] = a;
        }
        __syncthreads();
        for (int idx = t; idx < 1024; idx += 256) {   // T[x][k] = sum_y A[k][y]*F[x][y]
            int xx = idx >> 5, k = idx & 31;
            float acc = 0.f;
            #pragma unroll
            for (int y = 0; y < 32; y++) acc += sAt[y * 32 + k] * F[xx * 32 + y];
            T[idx] = acc;
        }
        __syncthreads();
        for (int idx = t; idx < 1024; idx += 256) {   // B[i][k] = sum_x A[i][x]*T[x][k]
            int i = idx >> 5, k = idx & 31;
            float acc = 0.f;
            #pragma unroll
            for (int xx = 0; xx < 32; xx++) acc += sA[i * 32 + xx] * T[xx * 32 + k];
            int f = idx * 512 + c;                    // flat gus index [p][c]
            int d = (f & 1023) * 1024 + (f >> 10);    // cat^T [q][i]
            __half h, l;
            split_h(acc, h, l);
            g_ch[d] = h;
            g_cl[d] = l;
        }
    } else {
        float (*tile)[33] = (float(*)[33])sbuf;
        int bid = blockIdx.x - 512;
        int p0 = (bid & 31) * 32, c0 = (bid >> 5) * 32;
        int tx = t & 31, ty = t >> 5;
        #pragma unroll
        for (int j = 0; j < 4; j++) {
            int ch = c0 + ty + j * 8;
            tile[ty + j * 8][tx] = x[ch * 1024 + p0 + tx] * g_s[ch];
        }
        __syncthreads();
        #pragma unroll
        for (int j = 0; j < 4; j++) {
            int p = p0 + ty + j * 8;
            float v = tile[tx][ty + j * 8];
            g_f0t[p * 512 + c0 + tx] = v;
            g_sigt[p * 512 + c0 + tx] = 1.f / (1.f + expf(-v));
        }
    }
}

// ---------------- 4. 3x3 patch-correlation attention ----------------
__global__ void k_csa() {
    int pix = blockIdx.x, pi = pix >> 5, pj = pix & 31;
    int t = threadIdx.x;
    int base = pix * 512 + t;
    __shared__ float wsum[8][9];
    __shared__ float sa[9];

    float sc0 = g_sigt[base];
    float sc1 = g_sigt[base + 256];

    bool okU = pi > 0, okD = pi < 31, okL = pj > 0, okR = pj < 31;
    bool ok[9];
    ok[0] = okU && okL; ok[1] = okU; ok[2] = okU && okR;
    ok[3] = okL;        ok[4] = true; ok[5] = okR;
    ok[6] = okD && okL; ok[7] = okD; ok[8] = okD && okR;
    const int off[9] = { -33*512, -32*512, -31*512, -1*512, 0, 1*512, 31*512, 32*512, 33*512 };

    float acc[9];
    #pragma unroll
    for (int uv = 0; uv < 9; uv++) {
        acc[uv] = ok[uv]
            ? sc0 * g_sigt[base + off[uv]] + sc1 * g_sigt[base + off[uv] + 256]
            : 0.f;
    }
    #pragma unroll
    for (int uv = 0; uv < 9; uv++)
        #pragma unroll
        for (int o = 16; o; o >>= 1) acc[uv] += __shfl_down_sync(0xffffffffu, acc[uv], o);
    if ((t & 31) == 0) {
        #pragma unroll
        for (int uv = 0; uv < 9; uv++) wsum[t >> 5][uv] = acc[uv];
    }
    __syncthreads();
    if (t < 32) {
        float v = -1e30f;
        if (t < 9) {
            float s2 = 0.f;
            #pragma unroll
            for (int w = 0; w < 8; w++) s2 += wsum[w][t];
            v = s2 * (1.f / 512.f);
        }
        float m = v;
        #pragma unroll
        for (int o = 16; o; o >>= 1) m = fmaxf(m, __shfl_xor_sync(0xffffffffu, m, o));
        float e = (t < 9) ? expf(v - m) : 0.f;
        float tot = e;
        #pragma unroll
        for (int o = 16; o; o >>= 1) tot += __shfl_xor_sync(0xffffffffu, tot, o);
        if (t < 9) sa[t] = e / tot;
    }
    __syncthreads();

    float o0 = 0.f, o1 = 0.f;
    #pragma unroll
    for (int uv = 0; uv < 9; uv++) {
        if (ok[uv]) {
            float a = sa[uv];
            o0 += a * g_f0t[base + off[uv]];
            o1 += a * g_f0t[base + off[uv] + 256];
        }
    }
    int f0i = 524288 + base;
    int f1i = 524288 + base + 256;
    int d0 = (f0i & 1023) * 1024 + (f0i >> 10);
    int d1 = (f1i & 1023) * 1024 + (f1i >> 10);
    __half h, l;
    split_h(o0, h, l); g_ch[d0] = h; g_cl[d0] = l;
    split_h(o1, h, l); g_ch[d1] = h; g_cl[d1] = l;
}

// ---------------- 5. down GEMM: fp16-split mma.sync.m16n8k16 ----------------
// z[512,1024] = W @ cat. Block 64x64 (grid 16x8), 8 warps (4 in M x 2 in N),
// warp tile 16x32. K chunks of 32, cp.async 2-stage, ldmatrix fragments.
// 3 terms: Wh*Ch + Wh*Cl + Wl*Ch, fp32 accumulate.
#define PLN 40            // smem row pitch in halves (80B, 16B-aligned, conflict-free)
#define PLANE_B (64 * PLN * 2)   // 5120 B per plane
#define STAGE_B (4 * PLANE_B)    // 20480 B per stage

__global__ void __launch_bounds__(256) k_gemm(float* __restrict__ out) {
    __shared__ __align__(16) __half sm[2][4][64 * PLN];  // [stage][Ah,Al,Bh,Bl]
    int t = threadIdx.x, lane = t & 31, w = t >> 5;
    int mbase = (w >> 1) * 16, nbase = (w & 1) * 32;
    int m0 = blockIdx.y * 64, n0 = blockIdx.x * 64;
    uint32_t smb = smem_u32(&sm[0][0][0]);

    // cp.async: 4 planes x 256 segs of 16B; thread t copies seg t of each plane
    int crow = t >> 2, cseg = t & 3;
    const __half* srcp[4] = {
        g_Wh + (m0 + crow) * 1024 + cseg * 8,
        g_Wl + (m0 + crow) * 1024 + cseg * 8,
        g_ch + (n0 + crow) * 1024 + cseg * 8,
        g_cl + (n0 + crow) * 1024 + cseg * 8
    };
    uint32_t doff = crow * (PLN * 2) + cseg * 16;

    // ldmatrix lane addressing: tile row r, m/n half, k half
    int r = lane & 7, h8 = (lane >> 3) & 1, kh = lane >> 4;
    uint32_t aoffH = 0 * PLANE_B + (mbase + h8 * 8 + r) * (PLN * 2) + kh * 16;
    uint32_t aoffL = 1 * PLANE_B + (mbase + h8 * 8 + r) * (PLN * 2) + kh * 16;
    uint32_t boffH[2], boffL[2];
    #pragma unroll
    for (int ng = 0; ng < 2; ng++) {
        boffH[ng] = 2 * PLANE_B + (nbase + ng * 16 + h8 * 8 + r) * (PLN * 2) + kh * 16;
        boffL[ng] = 3 * PLANE_B + (nbase + ng * 16 + h8 * 8 + r) * (PLN * 2) + kh * 16;
    }

    float acc[4][4] = {};

    // prologue: stage 0 = K chunk 0
    #pragma unroll
    for (int j = 0; j < 4; j++) CPA16(smb + j * PLANE_B + doff, srcp[j]);
    CPA_COMMIT();

    #pragma unroll 1
    for (int i = 0; i < 32; i++) {
        CPA_WAIT0();
        __syncthreads();
        if (i < 31) {
            uint32_t sb1 = smb + ((i + 1) & 1) * STAGE_B;
            const __half* so = (const __half*)0 + (i + 1) * 32;  // +32 halves offset
            #pragma unroll
            for (int j = 0; j < 4; j++) CPA16(sb1 + j * PLANE_B + doff, srcp[j] + (i + 1) * 32);
            CPA_COMMIT();
            (void)so;
        }
        uint32_t sb = smb + (i & 1) * STAGE_B;
        #pragma unroll
        for (int kk = 0; kk < 2; kk++) {
            uint32_t ko = kk * 32;   // 16 halves = 32 bytes
            uint32_t ah[4], al[4];
            LDMX4(ah, sb + aoffH + ko);
            LDMX4(al, sb + aoffL + ko);
            #pragma unroll
            for (int ng = 0; ng < 2; ng++) {
                uint32_t bh[4], bl[4];
                LDMX4(bh, sb + boffH[ng] + ko);
                LDMX4(bl, sb + boffL[ng] + ko);
                MMA16(acc[ng * 2],     ah, bh[0], bh[2]);
                MMA16(acc[ng * 2],     ah, bl[0], bl[2]);
                MMA16(acc[ng * 2],     al, bh[0], bh[2]);
                MMA16(acc[ng * 2 + 1], ah, bh[1], bh[3]);
                MMA16(acc[ng * 2 + 1], ah, bl[1], bl[3]);
                MMA16(acc[ng * 2 + 1], al, bh[1], bh[3]);
            }
        }
    }
    // epilogue: c0,c1 -> (row g, col 2q,2q+1); c2,c3 -> (row g+8, ...)
    int g = lane >> 2, q = lane & 3;
    int row = m0 + mbase + g;
    #pragma unroll
    for (int n8 = 0; n8 < 4; n8++) {
        int col = n0 + nbase + n8 * 8 + 2 * q;
        *(float2*)(out + row * 1024 + col)       = make_float2(acc[n8][0], acc[n8][1]);
        *(float2*)(out + (row + 8) * 1024 + col) = make_float2(acc[n8][2], acc[n8][3]);
    }
}

// ---------------- 6. instance norm + leaky relu (in place) ----------------
__global__ void k_norm(float* __restrict__ out) {
    int o = blockIdx.x, t = threadIdx.x;
    float4* row = (float4*)(out + o * 1024);
    float4 v = row[t];
    float s = v.x + v.y + v.z + v.w;
    float ss = v.x * v.x + v.y * v.y + v.z * v.z + v.w * v.w;
    #pragma unroll
    for (int off = 16; off; off >>= 1) {
        s  += __shfl_down_sync(0xffffffffu, s, off);
        ss += __shfl_down_sync(0xffffffffu, ss, off);
    }
    __shared__ float w1s[8], w2s[8];
    __shared__ float smean, sinv;
    if ((t & 31) == 0) { w1s[t >> 5] = s; w2s[t >> 5] = ss; }
    __syncthreads();
    if (t == 0) {
        float ts = 0.f, tss = 0.f;
        #pragma unroll
        for (int i = 0; i < 8; i++) { ts += w1s[i]; tss += w2s[i]; }
        float mu = ts * (1.f / 1024.f);
        float var = tss * (1.f / 1024.f) - mu * mu;
        smean = mu;
        sinv = 1.f / sqrtf(var + 1e-5f);
    }
    __syncthreads();
    float mu = smean, inv = sinv;
    float a;
    a = (v.x - mu) * inv; v.x = a >= 0.f ? a : 0.2f * a;
    a = (v.y - mu) * inv; v.y = a >= 0.f ? a : 0.2f * a;
    a = (v.z - mu) * inv; v.z = a >= 0.f ? a : 0.2f * a;
    a = (v.w - mu) * inv; v.w = a >= 0.f ? a : 0.2f * a;
    row[t] = v;
}

// ---------------- launch ----------------
extern "C" void kernel_launch(void* const* d_in, const int* in_sizes, int n_in,
                              void* d_out, int out_size) {
    const float* x  = (const float*)d_in[0];   // (1,512,32,32)
    const float* w1 = (const float*)d_in[1];   // (32,512)
    const float* b1 = (const float*)d_in[2];   // (32)
    const float* w2 = (const float*)d_in[3];   // (512,32)
    const float* b2 = (const float*)d_in[4];   // (512)
    const float* dw = (const float*)d_in[5];   // (512,1024)
    float* out = (float*)d_out;                // (1,512,32,32) fp32

    k_mean_initA<<<1025, 256>>>(x, dw);
    k_mlp<<<1, 1024>>>(w1, b1, w2, b2);
    k_gauss_trans<<<1024, 256>>>(x);
    k_csa<<<1024, 256>>>();
    k_gemm<<<dim3(16, 8), 256>>>(out);
    k_norm<<<512, 256>>>(out);
}

// round 11
// speedup vs baseline: 1.8857x; 1.0290x over previous
#include <cuda_runtime.h>
#include <cuda_fp16.h>
#include <stdint.h>
#include <math.h>

#define NC 512
#define NPIX 1024

// ---------------- scratch (no allocations allowed) ----------------
__device__ float g_y[NC];                   // channel means
__device__ float g_s[NC];                   // SE scales
__device__ float g_A[32 * 32];              // gaussian matrix A[i][x]
__device__ float g_f0t[NPIX * NC];          // f0 transposed: [pix][ch]
__device__ float g_sigt[NPIX * NC];         // sigmoid(f0): [pix][ch]
__device__ __half g_Wh[NC * 1024];          // W fp16 hi, [o][i] k-major
__device__ __half g_Wl[NC * 1024];          // W fp16 residual
__device__ __half g_ch[1024 * 1024];        // cat fp16 hi, NATURAL flat layout [i][p]
__device__ __half g_cl[1024 * 1024];        // cat fp16 residual

// ---------------- helpers ----------------
__device__ __forceinline__ uint32_t smem_u32(const void* p) {
    uint32_t a;
    asm("{ .reg .u64 t; cvta.to.shared.u64 t, %1; cvt.u32.u64 %0, t; }" : "=r"(a) : "l"(p));
    return a;
}
#define CPA16(sm, g) asm volatile("cp.async.ca.shared.global [%0], [%1], 16;" :: "r"(sm), "l"(g))
#define CPA_COMMIT()  asm volatile("cp.async.commit_group;" ::: "memory")
#define CPA_WAIT0()   asm volatile("cp.async.wait_group 0;" ::: "memory")

#define LDMX4(r, a) \
    asm volatile("ldmatrix.sync.aligned.m8n8.x4.shared.b16 {%0,%1,%2,%3}, [%4];" \
                 : "=r"((r)[0]), "=r"((r)[1]), "=r"((r)[2]), "=r"((r)[3]) : "r"(a))
#define LDMX4T(r, a) \
    asm volatile("ldmatrix.sync.aligned.m8n8.x4.trans.shared.b16 {%0,%1,%2,%3}, [%4];" \
                 : "=r"((r)[0]), "=r"((r)[1]), "=r"((r)[2]), "=r"((r)[3]) : "r"(a))

#define MMA16(d, a, b0v, b1v) \
    asm volatile("mma.sync.aligned.m16n8k16.row.col.f32.f16.f16.f32 " \
                 "{%0,%1,%2,%3},{%4,%5,%6,%7},{%8,%9},{%0,%1,%2,%3};" \
                 : "+f"((d)[0]), "+f"((d)[1]), "+f"((d)[2]), "+f"((d)[3]) \
                 : "r"((a)[0]), "r"((a)[1]), "r"((a)[2]), "r"((a)[3]), "r"(b0v), "r"(b1v))

__device__ __forceinline__ void split_h(float f, __half& h, __half& l) {
    h = __float2half_rn(f);
    l = __float2half_rn(f - __half2float(h));
}

// ---------------- 1. per-channel mean (0..511) + gaussian A (512) + W fp16-split (513..1024) ----------------
__global__ void k_mean_initA(const float* __restrict__ x, const float* __restrict__ dw) {
    int t = threadIdx.x;
    if (blockIdx.x < 512) {
        int c = blockIdx.x;
        float4 v = ((const float4*)(x + c * 1024))[t];
        float s = v.x + v.y + v.z + v.w;
        #pragma unroll
        for (int o = 16; o; o >>= 1) s += __shfl_down_sync(0xffffffffu, s, o);
        __shared__ float ws[8];
        if ((t & 31) == 0) ws[t >> 5] = s;
        __syncthreads();
        if (t == 0) {
            float tot = 0.f;
            #pragma unroll
            for (int i = 0; i < 8; i++) tot += ws[i];
            g_y[c] = tot * (1.f / 1024.f);
        }
    } else if (blockIdx.x == 512) {
        __shared__ double srow[32];
        if (t < 32) {
            double s = 0.0;
            for (int xx = 0; xx < 32; xx++) {
                double d = (double)(xx - t);
                s += exp(-d * d / 4.5);
            }
            srow[t] = s;
        }
        __syncthreads();
        for (int idx = t; idx < 1024; idx += 256) {
            int i = idx >> 5, xx = idx & 31;
            double d = (double)(xx - i);
            g_A[idx] = (float)(exp(-d * d / 4.5) / srow[i]);
        }
    } else {
        int row = blockIdx.x - 513;   // 0..511
        #pragma unroll
        for (int j = 0; j < 4; j++) {
            int idx = row * 1024 + t + j * 256;
            __half h, l;
            split_h(dw[idx], h, l);
            g_Wh[idx] = h;
            g_Wl[idx] = l;
        }
    }
}

// ---------------- 2. SE MLP: 512 -> 32 (relu) -> 512 (sigmoid) ----------------
__global__ void k_mlp(const float* __restrict__ w1, const float* __restrict__ b1,
                      const float* __restrict__ w2, const float* __restrict__ b2) {
    __shared__ float sy[512];
    __shared__ float sh[32];
    int t = threadIdx.x;
    if (t < 512) sy[t] = g_y[t];
    __syncthreads();
    int r = t >> 5, lane = t & 31;
    float a = 0.f;
    for (int c = lane; c < 512; c += 32) a += sy[c] * w1[r * 512 + c];
    #pragma unroll
    for (int o = 16; o; o >>= 1) a += __shfl_down_sync(0xffffffffu, a, o);
    if (lane == 0) sh[r] = fmaxf(a + b1[r], 0.f);
    __syncthreads();
    if (t < 512) {
        float acc = b2[t];
        #pragma unroll
        for (int rr = 0; rr < 32; rr++) acc += sh[rr] * w2[t * 32 + rr];
        g_s[t] = 1.f / (1.f + expf(-acc));
    }
}

// ---------------- 3. fused: gaussian pooling (0..511) + scale/transpose/sigmoid (512..1023) ----------------
__global__ void k_gauss_trans(const float* __restrict__ x) {
    __shared__ float sbuf[4096];
    int t = threadIdx.x;
    if (blockIdx.x < 512) {
        float* F   = sbuf;
        float* T   = sbuf + 1024;
        float* sA  = sbuf + 2048;
        float* sAt = sbuf + 3072;
        int c = blockIdx.x;
        float s = g_s[c];
        for (int i = t; i < 1024; i += 256) {
            F[i] = x[c * 1024 + i] * s;
            float a = g_A[i];
            sA[i] = a;
            sAt[(i & 31) * 32 + (i >> 5)] = a;
        }
        __syncthreads();
        for (int idx = t; idx < 1024; idx += 256) {   // T[x][k] = sum_y A[k][y]*F[x][y]
            int xx = idx >> 5, k = idx & 31;
            float acc = 0.f;
            #pragma unroll
            for (int y = 0; y < 32; y++) acc += sAt[y * 32 + k] * F[xx * 32 + y];
            T[idx] = acc;
        }
        __syncthreads();
        for (int idx = t; idx < 1024; idx += 256) {   // B[i][k] = sum_x A[i][x]*T[x][k]
            int i = idx >> 5, k = idx & 31;
            float acc = 0.f;
            #pragma unroll
            for (int xx = 0; xx < 32; xx++) acc += sA[i * 32 + xx] * T[xx * 32 + k];
            int f = idx * 512 + c;                    // flat cat index (natural layout)
            __half h, l;
            split_h(acc, h, l);
            g_ch[f] = h;
            g_cl[f] = l;
        }
    } else {
        float (*tile)[33] = (float(*)[33])sbuf;
        int bid = blockIdx.x - 512;
        int p0 = (bid & 31) * 32, c0 = (bid >> 5) * 32;
        int tx = t & 31, ty = t >> 5;
        #pragma unroll
        for (int j = 0; j < 4; j++) {
            int ch = c0 + ty + j * 8;
            tile[ty + j * 8][tx] = x[ch * 1024 + p0 + tx] * g_s[ch];
        }
        __syncthreads();
        #pragma unroll
        for (int j = 0; j < 4; j++) {
            int p = p0 + ty + j * 8;
            float v = tile[tx][ty + j * 8];
            g_f0t[p * 512 + c0 + tx] = v;
            g_sigt[p * 512 + c0 + tx] = 1.f / (1.f + expf(-v));
        }
    }
}

// ---------------- 4. 3x3 patch-correlation attention (coalesced fp16 stores) ----------------
__global__ void k_csa() {
    int pix = blockIdx.x, pi = pix >> 5, pj = pix & 31;
    int t = threadIdx.x;
    int base = pix * 512 + t;
    __shared__ float wsum[8][9];
    __shared__ float sa[9];

    float sc0 = g_sigt[base];
    float sc1 = g_sigt[base + 256];

    bool okU = pi > 0, okD = pi < 31, okL = pj > 0, okR = pj < 31;
    bool ok[9];
    ok[0] = okU && okL; ok[1] = okU; ok[2] = okU && okR;
    ok[3] = okL;        ok[4] = true; ok[5] = okR;
    ok[6] = okD && okL; ok[7] = okD; ok[8] = okD && okR;
    const int off[9] = { -33*512, -32*512, -31*512, -1*512, 0, 1*512, 31*512, 32*512, 33*512 };

    float acc[9];
    #pragma unroll
    for (int uv = 0; uv < 9; uv++) {
        acc[uv] = ok[uv]
            ? sc0 * g_sigt[base + off[uv]] + sc1 * g_sigt[base + off[uv] + 256]
            : 0.f;
    }
    #pragma unroll
    for (int uv = 0; uv < 9; uv++)
        #pragma unroll
        for (int o = 16; o; o >>= 1) acc[uv] += __shfl_down_sync(0xffffffffu, acc[uv], o);
    if ((t & 31) == 0) {
        #pragma unroll
        for (int uv = 0; uv < 9; uv++) wsum[t >> 5][uv] = acc[uv];
    }
    __syncthreads();
    if (t < 32) {
        float v = -1e30f;
        if (t < 9) {
            float s2 = 0.f;
            #pragma unroll
            for (int w = 0; w < 8; w++) s2 += wsum[w][t];
            v = s2 * (1.f / 512.f);
        }
        float m = v;
        #pragma unroll
        for (int o = 16; o; o >>= 1) m = fmaxf(m, __shfl_xor_sync(0xffffffffu, m, o));
        float e = (t < 9) ? expf(v - m) : 0.f;
        float tot = e;
        #pragma unroll
        for (int o = 16; o; o >>= 1) tot += __shfl_xor_sync(0xffffffffu, tot, o);
        if (t < 9) sa[t] = e / tot;
    }
    __syncthreads();

    float o0 = 0.f, o1 = 0.f;
    #pragma unroll
    for (int uv = 0; uv < 9; uv++) {
        if (ok[uv]) {
            float a = sa[uv];
            o0 += a * g_f0t[base + off[uv]];
            o1 += a * g_f0t[base + off[uv] + 256];
        }
    }
    __half h, l;
    split_h(o0, h, l); g_ch[524288 + base] = h;       g_cl[524288 + base] = l;
    split_h(o1, h, l); g_ch[524288 + base + 256] = h; g_cl[524288 + base + 256] = l;
}

// ---------------- 5. down GEMM: fp16-split mma.sync, B via ldmatrix.trans ----------------
// z[512,1024] = W @ cat. Block 64x64 (grid 16x8), 8 warps (4 M x 2 N), warp tile 16x32.
// K chunks of 32, cp.async 2-stage. A [m][k] pitch 80B; B [k][n] pitch 144B (trans reads).
// 3 terms: Wh*Ch + Wh*Cl + Wl*Ch, fp32 accumulate.
#define AP 40                     // A pitch (halves)
#define BP 72                     // B pitch (halves)
#define A_PLANE (64 * AP)         // 2560 halves
#define B_PLANE (32 * BP)         // 2304 halves
#define ST_H (2 * A_PLANE + 2 * B_PLANE)   // 9728 halves per stage
#define OAH 0
#define OAL A_PLANE
#define OBH (2 * A_PLANE)
#define OBL (2 * A_PLANE + B_PLANE)

__global__ void __launch_bounds__(256) k_gemm(float* __restrict__ out) {
    __shared__ __align__(16) __half sm[2 * ST_H];
    int t = threadIdx.x, lane = t & 31, w = t >> 5;
    int mbase = (w >> 1) * 16, nbase = (w & 1) * 32;
    int m0 = blockIdx.y * 64, n0 = blockIdx.x * 64;
    uint32_t smb = smem_u32(sm);

    // cp.async indices: A 64 rows x 4 segs of 16B; B 32 rows x 8 segs of 16B
    int arow = t >> 2, aseg = t & 3;
    int brow = t >> 3, bseg = t & 7;
    const __half* aSrcH = g_Wh + (m0 + arow) * 1024 + aseg * 8;
    const __half* aSrcL = g_Wl + (m0 + arow) * 1024 + aseg * 8;
    const __half* bSrcH = g_ch + brow * 1024 + n0 + bseg * 8;
    const __half* bSrcL = g_cl + brow * 1024 + n0 + bseg * 8;
    uint32_t aDst = arow * (AP * 2) + aseg * 16;
    uint32_t bDst = brow * (BP * 2) + bseg * 16;

    // A fragment lane addressing (non-trans): tiles (m0,k0),(m0+8,k0),(m0,k0+8),(m0+8,k0+8)
    int ar = lane & 7, ah8 = (lane >> 3) & 1, akh = lane >> 4;
    uint32_t aoffH = OAH * 2 + (mbase + ah8 * 8 + ar) * (AP * 2) + akh * 16;
    uint32_t aoffL = OAL * 2 + (mbase + ah8 * 8 + ar) * (AP * 2) + akh * 16;
    // B fragment lane addressing (trans): tiles (k0,n0),(k0+8,n0),(k0,n0+8),(k0+8,n0+8)
    int br = lane & 7, bk8 = (lane >> 3) & 1, bn8 = lane >> 4;
    uint32_t boffH[2], boffL[2];
    #pragma unroll
    for (int ng = 0; ng < 2; ng++) {
        uint32_t col2 = (nbase + ng * 16 + bn8 * 8) * 2;
        boffH[ng] = OBH * 2 + (bk8 * 8 + br) * (BP * 2) + col2;
        boffL[ng] = OBL * 2 + (bk8 * 8 + br) * (BP * 2) + col2;
    }

    float acc[4][4] = {};

    // prologue: stage 0 = K chunk 0
    CPA16(smb + OAH * 2 + aDst, aSrcH);
    CPA16(smb + OAL * 2 + aDst, aSrcL);
    CPA16(smb + OBH * 2 + bDst, bSrcH);
    CPA16(smb + OBL * 2 + bDst, bSrcL);
    CPA_COMMIT();

    #pragma unroll 1
    for (int i = 0; i < 32; i++) {
        CPA_WAIT0();
        __syncthreads();
        if (i < 31) {
            uint32_t sb1 = smb + ((i + 1) & 1) * (ST_H * 2);
            int kc = (i + 1) * 32;
            CPA16(sb1 + OAH * 2 + aDst, aSrcH + kc);
            CPA16(sb1 + OAL * 2 + aDst, aSrcL + kc);
            CPA16(sb1 + OBH * 2 + bDst, bSrcH + kc * 1024);
            CPA16(sb1 + OBL * 2 + bDst, bSrcL + kc * 1024);
            CPA_COMMIT();
        }
        uint32_t sb = smb + (i & 1) * (ST_H * 2);
        #pragma unroll
        for (int kk = 0; kk < 2; kk++) {
            uint32_t ako = kk * 32;              // A: +16 halves along k
            uint32_t bko = kk * 16 * (BP * 2);   // B: +16 k-rows
            uint32_t ah[4], al[4];
            LDMX4(ah, sb + aoffH + ako);
            LDMX4(al, sb + aoffL + ako);
            #pragma unroll
            for (int ng = 0; ng < 2; ng++) {
                uint32_t bh[4], bl[4];
                LDMX4T(bh, sb + boffH[ng] + bko);
                LDMX4T(bl, sb + boffL[ng] + bko);
                MMA16(acc[ng * 2],     ah, bh[0], bh[1]);
                MMA16(acc[ng * 2],     ah, bl[0], bl[1]);
                MMA16(acc[ng * 2],     al, bh[0], bh[1]);
                MMA16(acc[ng * 2 + 1], ah, bh[2], bh[3]);
                MMA16(acc[ng * 2 + 1], ah, bl[2], bl[3]);
                MMA16(acc[ng * 2 + 1], al, bh[2], bh[3]);
            }
        }
    }
    // epilogue: c0,c1 -> (row g, col 2q,2q+1); c2,c3 -> (row g+8, ...)
    int g = lane >> 2, q = lane & 3;
    int row = m0 + mbase + g;
    #pragma unroll
    for (int n8 = 0; n8 < 4; n8++) {
        int col = n0 + nbase + n8 * 8 + 2 * q;
        *(float2*)(out + row * 1024 + col)       = make_float2(acc[n8][0], acc[n8][1]);
        *(float2*)(out + (row + 8) * 1024 + col) = make_float2(acc[n8][2], acc[n8][3]);
    }
}

// ---------------- 6. instance norm + leaky relu (in place) ----------------
__global__ void k_norm(float* __restrict__ out) {
    int o = blockIdx.x, t = threadIdx.x;
    float4* row = (float4*)(out + o * 1024);
    float4 v = row[t];
    float s = v.x + v.y + v.z + v.w;
    float ss = v.x * v.x + v.y * v.y + v.z * v.z + v.w * v.w;
    #pragma unroll
    for (int off = 16; off; off >>= 1) {
        s  += __shfl_down_sync(0xffffffffu, s, off);
        ss += __shfl_down_sync(0xffffffffu, ss, off);
    }
    __shared__ float w1s[8], w2s[8];
    __shared__ float smean, sinv;
    if ((t & 31) == 0) { w1s[t >> 5] = s; w2s[t >> 5] = ss; }
    __syncthreads();
    if (t == 0) {
        float ts = 0.f, tss = 0.f;
        #pragma unroll
        for (int i = 0; i < 8; i++) { ts += w1s[i]; tss += w2s[i]; }
        float mu = ts * (1.f / 1024.f);
        float var = tss * (1.f / 1024.f) - mu * mu;
        smean = mu;
        sinv = 1.f / sqrtf(var + 1e-5f);
    }
    __syncthreads();
    float mu = smean, inv = sinv;
    float a;
    a = (v.x - mu) * inv; v.x = a >= 0.f ? a : 0.2f * a;
    a = (v.y - mu) * inv; v.y = a >= 0.f ? a : 0.2f * a;
    a = (v.z - mu) * inv; v.z = a >= 0.f ? a : 0.2f * a;
    a = (v.w - mu) * inv; v.w = a >= 0.f ? a : 0.2f * a;
    row[t] = v;
}

// ---------------- launch ----------------
extern "C" void kernel_launch(void* const* d_in, const int* in_sizes, int n_in,
                              void* d_out, int out_size) {
    const float* x  = (const float*)d_in[0];   // (1,512,32,32)
    const float* w1 = (const float*)d_in[1];   // (32,512)
    const float* b1 = (const float*)d_in[2];   // (32)
    const float* w2 = (const float*)d_in[3];   // (512,32)
    const float* b2 = (const float*)d_in[4];   // (512)
    const float* dw = (const float*)d_in[5];   // (512,1024)
    float* out = (float*)d_out;                // (1,512,32,32) fp32

    k_mean_initA<<<1025, 256>>>(x, dw);
    k_mlp<<<1, 1024>>>(w1, b1, w2, b2);
    k_gauss_trans<<<1024, 256>>>(x);
    k_csa<<<1024, 256>>>();
    k_gemm<<<dim3(16, 8), 256>>>(out);
    k_norm<<<512, 256>>>(out);
}